// round 1
// baseline (speedup 1.0000x reference)
#include <cuda_runtime.h>
#include <cstdint>

// ---------------------------------------------------------------------------
// ProtoTSNet on GB300 — round 1 (FP32 baseline, fused structure)
//
// Shapes: x[32,16,8192], enc_w[64,16,3], addon_w[64,64,1], protos[200,64,16],
//         last_w[10,200].  L1 = 8190 (after k=3 valid conv), Lo = 8175.
// Output: d_out[0..319]  = logits [32,10]
//         d_out[320..6719] = min_distances [32,200]
// ---------------------------------------------------------------------------

#define B_     32
#define FIN    16
#define L_     8192
#define LAT    64
#define L1_    8190   // L - 2
#define P_     200
#define KP     16
#define LO     8175   // L1 - 15
#define C_     10
#define EPS_   1e-4f

// scratch (static device globals; allocation-free)
__device__ float d_f[B_ * LAT * L1_];   // post-addon features  (~67 MB, bss)
__device__ float d_g[B_ * L_];          // per-(b,t) sum_c f^2
__device__ float d_p2[256];             // per-proto squared norm

// ---------------------------------------------------------------------------
// Kernel 1: fused encoder conv(k=3) + ReLU + addon 1x1 + ReLU + sum_c f^2
// grid (64 t-tiles, 32 b), 256 threads, dynamic smem
// ---------------------------------------------------------------------------
#define ENC_TT 128
#define ENC_XW 132      // padded width for x tile (need 130)
#define ENC_FW 132      // padded width for f1 tile
#define ENC_SMEM_FLOATS (FIN*ENC_XW + LAT*ENC_FW + LAT*FIN*3 + LAT*LAT)
#define ENC_SMEM_BYTES  (ENC_SMEM_FLOATS * 4)

__global__ void enc_addon_kernel(const float* __restrict__ x,
                                 const float* __restrict__ ew,
                                 const float* __restrict__ aw)
{
    extern __shared__ float sm[];
    float* xs  = sm;                       // [16][132]
    float* f1s = xs  + FIN * ENC_XW;       // [64][132]
    float* we  = f1s + LAT * ENC_FW;       // [64*16*3]
    float* wa  = we  + LAT * FIN * 3;      // [64*64]

    const int b  = blockIdx.y;
    const int t0 = blockIdx.x * ENC_TT;
    const int tid = threadIdx.x;

    for (int i = tid; i < LAT*FIN*3; i += 256) we[i] = ew[i];
    for (int i = tid; i < LAT*LAT;   i += 256) wa[i] = aw[i];
    for (int idx = tid; idx < FIN * 130; idx += 256) {
        int i = idx / 130, tt = idx % 130;
        int t = t0 + tt;
        xs[i * ENC_XW + tt] = (t < L_) ? x[(b * FIN + i) * L_ + t] : 0.f;
    }
    __syncthreads();

    const int t  = tid & 127;
    const int ch = tid >> 7;   // 0/1 -> channels [0,32) / [32,64)

    // ---- stage 1: encoder conv + relu ----
    float acc[32];
#pragma unroll
    for (int cc = 0; cc < 32; cc++) acc[cc] = 0.f;
    for (int i = 0; i < FIN; i++) {
        const float x0 = xs[i * ENC_XW + t];
        const float x1 = xs[i * ENC_XW + t + 1];
        const float x2 = xs[i * ENC_XW + t + 2];
#pragma unroll
        for (int cc = 0; cc < 32; cc++) {
            const float* wc = we + ((ch * 32 + cc) * FIN + i) * 3;
            acc[cc] += wc[0] * x0 + wc[1] * x1 + wc[2] * x2;
        }
    }
#pragma unroll
    for (int cc = 0; cc < 32; cc++)
        f1s[(ch * 32 + cc) * ENC_FW + t] = fmaxf(acc[cc], 0.f);
    __syncthreads();

    // ---- stage 2: 1x1 addon + relu + write f + accumulate g ----
    float acc2[32];
#pragma unroll
    for (int cc = 0; cc < 32; cc++) acc2[cc] = 0.f;
    for (int j = 0; j < LAT; j++) {
        const float fv = f1s[j * ENC_FW + t];
#pragma unroll
        for (int cc = 0; cc < 32; cc++)
            acc2[cc] += wa[(ch * 32 + cc) * LAT + j] * fv;
    }
    const int gt = t0 + t;
    float gp = 0.f;
#pragma unroll
    for (int cc = 0; cc < 32; cc++) {
        float v = fmaxf(acc2[cc], 0.f);
        if (gt < L1_) d_f[(b * LAT + ch * 32 + cc) * L1_ + gt] = v;
        gp += v * v;
    }
    __syncthreads();
    xs[tid] = gp;                 // reuse xs as reduction buffer
    __syncthreads();
    if (ch == 0 && gt < L1_)
        d_g[b * L_ + gt] = xs[t] + xs[t + 128];
}

// ---------------------------------------------------------------------------
// Kernel 2: per-proto squared norm
// ---------------------------------------------------------------------------
__global__ void p2_kernel(const float* __restrict__ protos)
{
    const int p = blockIdx.x;
    const int tid = threadIdx.x;
    float s = 0.f;
    for (int i = tid; i < LAT * KP; i += 256) {
        float v = protos[p * LAT * KP + i];
        s += v * v;
    }
#pragma unroll
    for (int o = 16; o; o >>= 1) s += __shfl_xor_sync(0xffffffffu, s, o);
    __shared__ float red[8];
    if ((tid & 31) == 0) red[tid >> 5] = s;
    __syncthreads();
    if (tid == 0) {
        float tsum = 0.f;
        for (int w = 0; w < 8; w++) tsum += red[w];
        d_p2[p] = tsum;
    }
}

// ---------------------------------------------------------------------------
// Kernel 3: init min-distance buffer (in d_out) to +inf
// ---------------------------------------------------------------------------
__global__ void init_kernel(unsigned* __restrict__ md)
{
    int i = blockIdx.x * 256 + threadIdx.x;
    if (i < B_ * P_) md[i] = 0x7f800000u;   // +inf
}

// ---------------------------------------------------------------------------
// Kernel 4: main fused GEMM + distance + min-reduce
//   xp[b,p,t] = sum_{c,k} f[b,c,t+k] * protos[p,c,k]
//   dist      = relu(s2[b,t] - 2*xp + p2[p]);  md[b,p] = min_t dist
// grid (64 t-tiles, 5 p-chunks, 32 b), 256 threads
// smem: protos chunk [40][1024] + f tile [64][144]  (~196 KB dynamic)
// ---------------------------------------------------------------------------
#define GPT 40
#define GTT 128
#define SFW 144
#define GEMM_SMEM_BYTES ((GPT * LAT * KP + LAT * SFW) * 4)

__global__ void gemm_min_kernel(const float* __restrict__ protos,
                                unsigned* __restrict__ md)
{
    extern __shared__ float sm[];
    float* sp = sm;                        // [40][1024]
    float* sf = sm + GPT * LAT * KP;       // [64][144]
    __shared__ float gs[160];              // g tile for s2

    const int b  = blockIdx.z;
    const int t0 = blockIdx.x * GTT;
    const int p0 = blockIdx.y * GPT;
    const int tid = threadIdx.x;

    // protos chunk is contiguous: float4 copy
    {
        const float4* src = (const float4*)(protos + p0 * LAT * KP);
        float4* dst = (float4*)sp;
        for (int i = tid; i < GPT * LAT * KP / 4; i += 256) dst[i] = src[i];
    }
    // f tile [64][143], zero-padded past L1
    for (int idx = tid; idx < LAT * 143; idx += 256) {
        int c = idx / 143, tt = idx % 143;
        int t = t0 + tt;
        sf[c * SFW + tt] = (t < L1_) ? d_f[(b * LAT + c) * L1_ + t] : 0.f;
    }
    // g tile for sliding sum
    if (tid < 143) {
        int t = t0 + tid;
        gs[tid] = (t < L1_) ? d_g[b * L_ + t] : 0.f;
    }
    __syncthreads();

    const int tx = tid & 31;     // t lane
    const int ty = tid >> 5;     // p group 0..7

    float acc[5][4];
#pragma unroll
    for (int i = 0; i < 5; i++)
#pragma unroll
        for (int j = 0; j < 4; j++) acc[i][j] = 0.f;

    const float* sp0 = sp + ty * (LAT * KP);     // stride 8*1024 between i's

    for (int c = 0; c < LAT; c++) {
        const float* sfc = sf + c * SFW + tx;
        const float* spc = sp0 + c * KP;
#pragma unroll
        for (int k = 0; k < KP; k++) {
            const float fv0 = sfc[k];
            const float fv1 = sfc[k + 32];
            const float fv2 = sfc[k + 64];
            const float fv3 = sfc[k + 96];
#pragma unroll
            for (int i = 0; i < 5; i++) {
                const float pv = spc[i * (8 * LAT * KP) + k];
                acc[i][0] += pv * fv0;
                acc[i][1] += pv * fv1;
                acc[i][2] += pv * fv2;
                acc[i][3] += pv * fv3;
            }
        }
    }

    // s2 per t (independent of p)
    float s2v[4];
#pragma unroll
    for (int j = 0; j < 4; j++) {
        float s = 0.f;
        const int base = tx + 32 * j;
#pragma unroll
        for (int k = 0; k < KP; k++) s += gs[base + k];
        s2v[j] = s;
    }

#pragma unroll
    for (int i = 0; i < 5; i++) {
        const int p = p0 + ty + 8 * i;
        const float pp = d_p2[p];
        float mn = __int_as_float(0x7f800000);
#pragma unroll
        for (int j = 0; j < 4; j++) {
            const int t = t0 + tx + 32 * j;
            if (t < LO) {
                float d = s2v[j] - 2.f * acc[i][j] + pp;
                d = fmaxf(d, 0.f);
                mn = fminf(mn, d);
            }
        }
#pragma unroll
        for (int o = 16; o; o >>= 1)
            mn = fminf(mn, __shfl_xor_sync(0xffffffffu, mn, o));
        if (tx == 0)
            atomicMin(&md[b * P_ + p], __float_as_uint(mn));
    }
}

// ---------------------------------------------------------------------------
// Kernel 5: head — log-similarity + last layer
// ---------------------------------------------------------------------------
__global__ void head_kernel(const float* __restrict__ lw,
                            float* __restrict__ out)
{
    __shared__ float acts[B_ * P_];
    const unsigned* mdb = (const unsigned*)(out + B_ * C_);
    const int tid = threadIdx.x;   // 320
    for (int i = tid; i < B_ * P_; i += 320) {
        float m = __uint_as_float(mdb[i]);
        acts[i] = logf((m + 1.0f) / (m + EPS_));
    }
    __syncthreads();
    if (tid < B_ * C_) {
        int bb = tid / C_, c = tid % C_;
        float s = 0.f;
        for (int p = 0; p < P_; p++)
            s += acts[bb * P_ + p] * lw[c * P_ + p];
        out[bb * C_ + c] = s;
    }
}

// ---------------------------------------------------------------------------
extern "C" void kernel_launch(void* const* d_in, const int* in_sizes, int n_in,
                              void* d_out, int out_size)
{
    const float* x      = (const float*)d_in[0];
    const float* enc_w  = (const float*)d_in[1];
    const float* addon_w= (const float*)d_in[2];
    const float* protos = (const float*)d_in[3];
    const float* last_w = (const float*)d_in[4];
    float* out = (float*)d_out;

    cudaFuncSetAttribute(enc_addon_kernel,
                         cudaFuncAttributeMaxDynamicSharedMemorySize,
                         ENC_SMEM_BYTES);
    cudaFuncSetAttribute(gemm_min_kernel,
                         cudaFuncAttributeMaxDynamicSharedMemorySize,
                         GEMM_SMEM_BYTES);

    unsigned* md = (unsigned*)(out + B_ * C_);

    init_kernel<<<(B_ * P_ + 255) / 256, 256>>>(md);
    p2_kernel<<<P_, 256>>>(protos);
    enc_addon_kernel<<<dim3(64, B_), 256, ENC_SMEM_BYTES>>>(x, enc_w, addon_w);
    gemm_min_kernel<<<dim3(64, 5, B_), 256, GEMM_SMEM_BYTES>>>(protos, md);
    head_kernel<<<1, 320>>>(last_w, out);
}

// round 3
// speedup vs baseline: 5.1286x; 5.1286x over previous
#include <cuda_runtime.h>
#include <cuda_bf16.h>
#include <cstdint>

// ---------------------------------------------------------------------------
// ProtoTSNet on GB300 — round 3: bf16 mma.sync (HMMA) proto-distance GEMM
// (tcgen05 unavailable: harness PTX target is sm_103 without the 'a' feature)
//
// out[0..319]    = logits [32,10]
// out[320..6719] = min_distances [32,200]
// ---------------------------------------------------------------------------

#define B_     32
#define FIN    16
#define L_     8192
#define LAT    64
#define L1_    8190
#define P_     200
#define KP     16
#define LO     8175
#define C_     10
#define EPS_   1e-4f
#define TPAD   8224

// ---------------- static device scratch (allocation-free) -----------------
__device__ __nv_bfloat16 d_fT[B_ * TPAD * LAT];    // f [b][t][c], bf16 (bss zero)
__device__ float         d_g [B_ * TPAD];          // sum_c f_bf16^2
__device__ __nv_bfloat16 d_protA[16 * 256 * LAT];  // protos [kk][p pad256][c]
__device__ float         d_p2[256];                // ||p||^2 (bf16-rounded)

// ---------------------------------------------------------------------------
// Kernel 1: fused enc conv(k=3)+ReLU + addon 1x1+ReLU -> d_fT (bf16) + d_g
// ---------------------------------------------------------------------------
#define ENC_XW 132
#define ENC_FW 132
#define ENC_SMEM_FLOATS (FIN*ENC_XW + LAT*ENC_FW + LAT*FIN*3 + LAT*LAT)
#define ENC_SMEM_BYTES  (ENC_SMEM_FLOATS * 4)

__global__ void enc_addon_kernel(const float* __restrict__ x,
                                 const float* __restrict__ ew,
                                 const float* __restrict__ aw)
{
    extern __shared__ float sm[];
    float* xs  = sm;
    float* f1s = xs  + FIN * ENC_XW;
    float* we  = f1s + LAT * ENC_FW;
    float* wa  = we  + LAT * FIN * 3;

    const int b  = blockIdx.y;
    const int t0 = blockIdx.x * 128;
    const int tid = threadIdx.x;

    for (int i = tid; i < LAT*FIN*3; i += 256) we[i] = ew[i];
    for (int i = tid; i < LAT*LAT;   i += 256) wa[i] = aw[i];
    for (int idx = tid; idx < FIN * 130; idx += 256) {
        int i = idx / 130, tt = idx % 130;
        int t = t0 + tt;
        xs[i * ENC_XW + tt] = (t < L_) ? x[(b * FIN + i) * L_ + t] : 0.f;
    }
    __syncthreads();

    const int t  = tid & 127;
    const int ch = tid >> 7;

    float acc[32];
#pragma unroll
    for (int cc = 0; cc < 32; cc++) acc[cc] = 0.f;
    for (int i = 0; i < FIN; i++) {
        const float x0 = xs[i * ENC_XW + t];
        const float x1 = xs[i * ENC_XW + t + 1];
        const float x2 = xs[i * ENC_XW + t + 2];
#pragma unroll
        for (int cc = 0; cc < 32; cc++) {
            const float* wc = we + ((ch * 32 + cc) * FIN + i) * 3;
            acc[cc] += wc[0] * x0 + wc[1] * x1 + wc[2] * x2;
        }
    }
#pragma unroll
    for (int cc = 0; cc < 32; cc++)
        f1s[(ch * 32 + cc) * ENC_FW + t] = fmaxf(acc[cc], 0.f);
    __syncthreads();

    float acc2[32];
#pragma unroll
    for (int cc = 0; cc < 32; cc++) acc2[cc] = 0.f;
    for (int j = 0; j < LAT; j++) {
        const float fv = f1s[j * ENC_FW + t];
#pragma unroll
        for (int cc = 0; cc < 32; cc++)
            acc2[cc] += wa[(ch * 32 + cc) * LAT + j] * fv;
    }

    const int gt = t0 + t;
    float gp = 0.f;
    unsigned pk[16];
#pragma unroll
    for (int j = 0; j < 16; j++) {
        float v0 = fmaxf(acc2[2*j],   0.f);
        float v1 = fmaxf(acc2[2*j+1], 0.f);
        __nv_bfloat162 h2 = __floats2bfloat162_rn(v0, v1);
        pk[j] = *reinterpret_cast<unsigned*>(&h2);
        float r0 = __bfloat162float(__low2bfloat16(h2));
        float r1 = __bfloat162float(__high2bfloat16(h2));
        gp += r0 * r0 + r1 * r1;
    }
    if (gt < L1_) {
        uint4* dst = reinterpret_cast<uint4*>(d_fT + ((size_t)b * TPAD + gt) * LAT + ch * 32);
        const uint4* src = reinterpret_cast<const uint4*>(pk);
#pragma unroll
        for (int q = 0; q < 4; q++) dst[q] = src[q];
    }
    __syncthreads();
    xs[tid] = gp;
    __syncthreads();
    if (ch == 0 && gt < L1_)
        d_g[b * TPAD + gt] = xs[t] + xs[t + 128];
}

// ---------------------------------------------------------------------------
// Kernel 2: rearrange protos -> d_protA [kk][p pad256][c], bf16
// ---------------------------------------------------------------------------
__global__ void protA_kernel(const float* __restrict__ protos)
{
    int idx = blockIdx.x * 256 + threadIdx.x;
    if (idx >= 16 * 256 * LAT) return;
    int c  = idx & 63;
    int pp = (idx >> 6) & 255;
    int kk = idx >> 14;
    float v = (pp < P_) ? protos[pp * (LAT * KP) + c * KP + kk] : 0.f;
    d_protA[idx] = __float2bfloat16(v);
}

// ---------------------------------------------------------------------------
// Kernel 3: p2 from bf16-rounded protos
// ---------------------------------------------------------------------------
__global__ void p2_kernel(const float* __restrict__ protos)
{
    const int p = blockIdx.x;
    const int tid = threadIdx.x;
    float s = 0.f;
    for (int i = tid; i < LAT * KP; i += 256) {
        float v = __bfloat162float(__float2bfloat16(protos[p * LAT * KP + i]));
        s += v * v;
    }
#pragma unroll
    for (int o = 16; o; o >>= 1) s += __shfl_xor_sync(0xffffffffu, s, o);
    __shared__ float red[8];
    if ((tid & 31) == 0) red[tid >> 5] = s;
    __syncthreads();
    if (tid == 0) {
        float ts = 0.f;
        for (int w = 0; w < 8; w++) ts += red[w];
        d_p2[p] = ts;
    }
}

__global__ void init_kernel(unsigned* __restrict__ md)
{
    int i = blockIdx.x * 256 + threadIdx.x;
    if (i < B_ * P_) md[i] = 0x7f800000u;
}

// ---------------------------------------------------------------------------
// Kernel 4: HMMA GEMM + distance + min-reduce
//   grid (32 t-tiles, 2 p-tiles, 32 b), 512 threads (16 warps, 4M x 4N)
//   CTA tile: M=128 p, N=256 t, K=1024 (16 taps x 64 c)
// ---------------------------------------------------------------------------
#define NT_       256
#define FROWS     272
#define ROWB      144                    // padded row stride (bytes)
#define SF_BYTES  (FROWS * ROWB)         // 39168
#define SP_TAP    (128 * ROWB)           // 18432
#define SP_BYTES  (4 * SP_TAP)           // 73728
#define GEMM_DYN  (SF_BYTES + SP_BYTES)  // 112896

__device__ __forceinline__ void mma16816(float* c, const uint32_t* a,
                                         const uint32_t* b)
{
    asm volatile(
        "mma.sync.aligned.m16n8k16.row.col.f32.bf16.bf16.f32 "
        "{%0,%1,%2,%3}, {%4,%5,%6,%7}, {%8,%9}, {%0,%1,%2,%3};"
        : "+f"(c[0]), "+f"(c[1]), "+f"(c[2]), "+f"(c[3])
        : "r"(a[0]), "r"(a[1]), "r"(a[2]), "r"(a[3]), "r"(b[0]), "r"(b[1]));
}

__global__ void __launch_bounds__(512, 1)
gemm_min_kernel(unsigned* __restrict__ md)
{
    extern __shared__ char dynsm[];
    char* sf = dynsm;                // f tile   [272 rows][144B]
    char* sp = dynsm + SF_BYTES;     // protos   [4 taps][128 rows][144B]

    __shared__ float    s_g[FROWS];
    __shared__ float    s2s[NT_];
    __shared__ float    s_p2[128];
    __shared__ unsigned s_md[128];

    const int b   = blockIdx.z;
    const int t0  = blockIdx.x * NT_;
    const int p0  = blockIdx.y * 128;
    const int tid = threadIdx.x;
    const int lane = tid & 31;
    const int wid  = tid >> 5;
    const int wm = wid & 3;          // p-block of 32
    const int wn = wid >> 2;         // t-block of 64
    const int g   = lane >> 2;       // group id 0..7
    const int tig = lane & 3;        // thread-in-group

    // ---- load f tile (t-major bf16 rows, padded stride 144B) ----
    const __nv_bfloat16* fT = d_fT + (size_t)b * TPAD * LAT;
    for (int i = tid; i < FROWS * 8; i += 512) {
        int r = i >> 3, seg = i & 7;
        uint4 v = *reinterpret_cast<const uint4*>(fT + (size_t)(t0 + r) * LAT + seg * 8);
        *reinterpret_cast<uint4*>(sf + r * ROWB + seg * 16) = v;
    }
    for (int i = tid; i < FROWS; i += 512) s_g[i] = d_g[b * TPAD + t0 + i];
    if (tid < 128) {
        s_p2[tid] = d_p2[p0 + tid];
        s_md[tid] = 0x7f800000u;
    }
    __syncthreads();
    if (tid < NT_) {
        float s = 0.f;
#pragma unroll
        for (int k = 0; k < KP; k++) s += s_g[tid + k];
        s2s[tid] = s;
    }

    float acc[2][8][4];
#pragma unroll
    for (int mt = 0; mt < 2; mt++)
#pragma unroll
        for (int nt = 0; nt < 8; nt++)
#pragma unroll
            for (int e = 0; e < 4; e++) acc[mt][nt][e] = 0.f;

    // thread-invariant fragment base offsets
    const char* a_base0 = sp + (wm * 32 + g) * ROWB + tig * 4;
    const char* b_base0 = sf + (wn * 64 + g) * ROWB + tig * 4;

    // ---- main loop: 4 phases x 4 taps x 4 c-chunks ----
    for (int ph = 0; ph < 4; ph++) {
        __syncthreads();   // previous phase's consumers done before overwrite
        for (int i = tid; i < 4096; i += 512) {
            int j = i >> 10, rs = i & 1023;
            int r = rs >> 3, seg = rs & 7;
            uint4 v = *reinterpret_cast<const uint4*>(
                d_protA + ((size_t)((ph * 4 + j) * 256 + p0 + r)) * LAT + seg * 8);
            *reinterpret_cast<uint4*>(sp + j * SP_TAP + r * ROWB + seg * 16) = v;
        }
        __syncthreads();

#pragma unroll
        for (int j = 0; j < 4; j++) {
            const int kk = ph * 4 + j;
            const char* aj = a_base0 + j * SP_TAP;
            const char* bj = b_base0 + kk * ROWB;
#pragma unroll
            for (int cc = 0; cc < 4; cc++) {
                uint32_t a[2][4], bf[8][2];
#pragma unroll
                for (int mt = 0; mt < 2; mt++) {
                    const char* ab = aj + mt * (16 * ROWB) + cc * 32;
                    a[mt][0] = *reinterpret_cast<const uint32_t*>(ab);
                    a[mt][1] = *reinterpret_cast<const uint32_t*>(ab + 8 * ROWB);
                    a[mt][2] = *reinterpret_cast<const uint32_t*>(ab + 16);
                    a[mt][3] = *reinterpret_cast<const uint32_t*>(ab + 8 * ROWB + 16);
                }
#pragma unroll
                for (int nt = 0; nt < 8; nt++) {
                    const char* bb = bj + nt * (8 * ROWB) + cc * 32;
                    bf[nt][0] = *reinterpret_cast<const uint32_t*>(bb);
                    bf[nt][1] = *reinterpret_cast<const uint32_t*>(bb + 16);
                }
#pragma unroll
                for (int mt = 0; mt < 2; mt++)
#pragma unroll
                    for (int nt = 0; nt < 8; nt++)
                        mma16816(acc[mt][nt], a[mt], bf[nt]);
            }
        }
    }

    // ---- epilogue: dist = relu(s2 - 2*xp + p2), min over t ----
#pragma unroll
    for (int mt = 0; mt < 2; mt++) {
#pragma unroll
        for (int half = 0; half < 2; half++) {
            const int pl = wm * 32 + mt * 16 + g + half * 8;   // local p
            const float pp = s_p2[pl];
            float mn = __int_as_float(0x7f800000);
#pragma unroll
            for (int nt = 0; nt < 8; nt++) {
#pragma unroll
                for (int e = 0; e < 2; e++) {
                    const int col = wn * 64 + nt * 8 + tig * 2 + e;
                    if (t0 + col < LO) {
                        float xp = acc[mt][nt][half * 2 + e];
                        float dd = fmaxf(s2s[col] - 2.f * xp + pp, 0.f);
                        mn = fminf(mn, dd);
                    }
                }
            }
            atomicMin(&s_md[pl], __float_as_uint(mn));
        }
    }
    __syncthreads();
    if (tid < 128 && p0 + tid < P_)
        atomicMin(&md[b * P_ + p0 + tid], s_md[tid]);
}

// ---------------------------------------------------------------------------
// Kernel 5: head
// ---------------------------------------------------------------------------
__global__ void head_kernel(const float* __restrict__ lw,
                            float* __restrict__ out)
{
    __shared__ float acts[B_ * P_];
    const unsigned* mdb = (const unsigned*)(out + B_ * C_);
    const int tid = threadIdx.x;
    for (int i = tid; i < B_ * P_; i += 320) {
        float m = __uint_as_float(mdb[i]);
        acts[i] = logf((m + 1.0f) / (m + EPS_));
    }
    __syncthreads();
    if (tid < B_ * C_) {
        int bb = tid / C_, c = tid % C_;
        float s = 0.f;
        for (int pidx = 0; pidx < P_; pidx++)
            s += acts[bb * P_ + pidx] * lw[c * P_ + pidx];
        out[bb * C_ + c] = s;
    }
}

// ---------------------------------------------------------------------------
extern "C" void kernel_launch(void* const* d_in, const int* in_sizes, int n_in,
                              void* d_out, int out_size)
{
    const float* x       = (const float*)d_in[0];
    const float* enc_w   = (const float*)d_in[1];
    const float* addon_w = (const float*)d_in[2];
    const float* protos  = (const float*)d_in[3];
    const float* last_w  = (const float*)d_in[4];
    float* out = (float*)d_out;

    cudaFuncSetAttribute(enc_addon_kernel,
                         cudaFuncAttributeMaxDynamicSharedMemorySize, ENC_SMEM_BYTES);
    cudaFuncSetAttribute(gemm_min_kernel,
                         cudaFuncAttributeMaxDynamicSharedMemorySize, GEMM_DYN);

    unsigned* md = (unsigned*)(out + B_ * C_);

    init_kernel<<<(B_ * P_ + 255) / 256, 256>>>(md);
    p2_kernel<<<P_, 256>>>(protos);
    protA_kernel<<<(16 * 256 * LAT + 255) / 256, 256>>>(protos);
    enc_addon_kernel<<<dim3(64, B_), 256, ENC_SMEM_BYTES>>>(x, enc_w, addon_w);
    gemm_min_kernel<<<dim3(32, 2, B_), 512, GEMM_DYN>>>(md);
    head_kernel<<<1, 320>>>(last_w, out);
}

// round 4
// speedup vs baseline: 6.6192x; 1.2906x over previous
#include <cuda_runtime.h>
#include <cuda_bf16.h>
#include <cstdint>

// ---------------------------------------------------------------------------
// ProtoTSNet on GB300 — round 4
//  - enc: register-blocked (4t x 16ch per thread), FFMA-bound
//  - gemm: ldmatrix.x4 fragments + cp.async double-buffered proto phases
//
// out[0..319]    = logits [32,10]
// out[320..6719] = min_distances [32,200]
// ---------------------------------------------------------------------------

#define B_     32
#define FIN    16
#define L_     8192
#define LAT    64
#define L1_    8190
#define P_     200
#define KP     16
#define LO     8175
#define C_     10
#define EPS_   1e-4f
#define TPAD   8224

// ---------------- static device scratch (allocation-free) -----------------
__device__ __nv_bfloat16 d_fT[B_ * TPAD * LAT];    // f [b][t][c], bf16
__device__ float         d_g [B_ * TPAD];          // sum_c f_bf16^2
__device__ __nv_bfloat16 d_protA[16 * 256 * LAT];  // protos [kk][p pad256][c]
__device__ float         d_p2[256];                // ||p||^2 (bf16-rounded)

__device__ __forceinline__ uint32_t smem_u32(const void* p) {
    uint32_t a;
    asm("{ .reg .u64 t; cvta.to.shared.u64 t, %1; cvt.u32.u64 %0, t; }"
        : "=r"(a) : "l"(p));
    return a;
}
__device__ __forceinline__ void cp16(uint32_t s, const void* g) {
    asm volatile("cp.async.cg.shared.global [%0], [%1], 16;" :: "r"(s), "l"(g));
}
#define CP_COMMIT() asm volatile("cp.async.commit_group;" ::: "memory")
#define CP_WAIT0()  asm volatile("cp.async.wait_group 0;" ::: "memory")

// ---------------------------------------------------------------------------
// Kernel 1: fused enc conv(k=3)+ReLU + addon 1x1+ReLU -> d_fT (bf16) + d_g
//   256 threads = 64 t-lanes x 4 ch-groups; each thread: 4 t x 16 ch
//   tile = 256 t per block, grid (32, B)
// ---------------------------------------------------------------------------
#define ET      256
#define XS_W    258
#define ENC_DYN ((16*XS_W + 64*ET + 64*16*3 + 64*64) * 4)   // 110720 B

__global__ void __launch_bounds__(256, 2)
enc_addon_kernel(const float* __restrict__ x,
                 const float* __restrict__ ew,
                 const float* __restrict__ aw)
{
    extern __shared__ float sm[];
    float* xs   = sm;                       // [16][258]  (later reused: gpart[4][256])
    float* f1s  = xs  + 16 * XS_W;          // [64][256]
    float* we   = f1s + 64 * ET;            // [64*16*3]
    float* wa   = we  + 64 * 16 * 3;        // [64*64]
    float* gpart = xs;                      // overlay

    const int b   = blockIdx.y;
    const int t0  = blockIdx.x * ET;
    const int tid = threadIdx.x;
    const int tl  = tid & 63;      // t-lane
    const int grp = tid >> 6;      // channel group (16 ch)

    for (int i = tid; i < 64*16*3; i += 256) we[i] = ew[i];
    for (int i = tid; i < 64*64;   i += 256) wa[i] = aw[i];
    for (int idx = tid; idx < 16 * XS_W; idx += 256) {
        int i = idx / XS_W, tt = idx - i * XS_W;
        int t = t0 + tt;
        xs[idx] = (t < L_) ? x[(b * FIN + i) * L_ + t] : 0.f;
    }
    __syncthreads();

    // ---- stage 1: encoder conv(k=3) + relu ----
    float acc[16][4];
#pragma unroll
    for (int cc = 0; cc < 16; cc++)
#pragma unroll
        for (int q = 0; q < 4; q++) acc[cc][q] = 0.f;

    for (int i = 0; i < FIN; i++) {
        float xv[4][3];
#pragma unroll
        for (int q = 0; q < 4; q++) {
            const float* xr = xs + i * XS_W + tl + 64 * q;
            xv[q][0] = xr[0]; xv[q][1] = xr[1]; xv[q][2] = xr[2];
        }
#pragma unroll
        for (int cc = 0; cc < 16; cc++) {
            const float* w = we + ((grp * 16 + cc) * FIN + i) * 3;
            const float w0 = w[0], w1 = w[1], w2 = w[2];
#pragma unroll
            for (int q = 0; q < 4; q++)
                acc[cc][q] += w0 * xv[q][0] + w1 * xv[q][1] + w2 * xv[q][2];
        }
    }
#pragma unroll
    for (int cc = 0; cc < 16; cc++)
#pragma unroll
        for (int q = 0; q < 4; q++)
            f1s[(grp * 16 + cc) * ET + tl + 64 * q] = fmaxf(acc[cc][q], 0.f);
    __syncthreads();

    // ---- stage 2: 1x1 addon + relu ----
#pragma unroll
    for (int cc = 0; cc < 16; cc++)
#pragma unroll
        for (int q = 0; q < 4; q++) acc[cc][q] = 0.f;

    for (int j = 0; j < LAT; j++) {
        float fv[4];
#pragma unroll
        for (int q = 0; q < 4; q++) fv[q] = f1s[j * ET + tl + 64 * q];
#pragma unroll
        for (int cc = 0; cc < 16; cc++) {
            const float w = wa[(grp * 16 + cc) * LAT + j];
#pragma unroll
            for (int q = 0; q < 4; q++) acc[cc][q] += w * fv[q];
        }
    }

    // ---- round to bf16, store f, accumulate per-group sum of squares ----
#pragma unroll
    for (int q = 0; q < 4; q++) {
        const int t = t0 + tl + 64 * q;
        float gp = 0.f;
        unsigned pk[8];
#pragma unroll
        for (int j = 0; j < 8; j++) {
            float v0 = fmaxf(acc[2*j][q],   0.f);
            float v1 = fmaxf(acc[2*j+1][q], 0.f);
            __nv_bfloat162 h2 = __floats2bfloat162_rn(v0, v1);
            pk[j] = *reinterpret_cast<unsigned*>(&h2);
            float r0 = __bfloat162float(__low2bfloat16(h2));
            float r1 = __bfloat162float(__high2bfloat16(h2));
            gp += r0 * r0 + r1 * r1;
        }
        if (t < L1_) {
            uint4* dst = reinterpret_cast<uint4*>(
                d_fT + ((size_t)b * TPAD + t) * LAT + grp * 16);
            dst[0] = *reinterpret_cast<const uint4*>(pk);
            dst[1] = *reinterpret_cast<const uint4*>(pk + 4);
        }
        gpart[grp * ET + tl + 64 * q] = gp;
    }
    __syncthreads();
    if (tid < ET) {
        const int t = t0 + tid;
        if (t < L1_)
            d_g[b * TPAD + t] = gpart[tid] + gpart[ET + tid] +
                                gpart[2*ET + tid] + gpart[3*ET + tid];
    }
}

// ---------------------------------------------------------------------------
// Kernel 2: rearrange protos -> d_protA [kk][p pad256][c], bf16
// ---------------------------------------------------------------------------
__global__ void protA_kernel(const float* __restrict__ protos)
{
    int idx = blockIdx.x * 256 + threadIdx.x;
    if (idx >= 16 * 256 * LAT) return;
    int c  = idx & 63;
    int pp = (idx >> 6) & 255;
    int kk = idx >> 14;
    float v = (pp < P_) ? protos[pp * (LAT * KP) + c * KP + kk] : 0.f;
    d_protA[idx] = __float2bfloat16(v);
}

// ---------------------------------------------------------------------------
// Kernel 3: p2 from bf16-rounded protos
// ---------------------------------------------------------------------------
__global__ void p2_kernel(const float* __restrict__ protos)
{
    const int p = blockIdx.x;
    const int tid = threadIdx.x;
    float s = 0.f;
    for (int i = tid; i < LAT * KP; i += 256) {
        float v = __bfloat162float(__float2bfloat16(protos[p * LAT * KP + i]));
        s += v * v;
    }
#pragma unroll
    for (int o = 16; o; o >>= 1) s += __shfl_xor_sync(0xffffffffu, s, o);
    __shared__ float red[8];
    if ((tid & 31) == 0) red[tid >> 5] = s;
    __syncthreads();
    if (tid == 0) {
        float ts = 0.f;
        for (int w = 0; w < 8; w++) ts += red[w];
        d_p2[p] = ts;
    }
}

__global__ void init_kernel(unsigned* __restrict__ md)
{
    int i = blockIdx.x * 256 + threadIdx.x;
    if (i < B_ * P_) md[i] = 0x7f800000u;
}

// ---------------------------------------------------------------------------
// Kernel 4: HMMA GEMM + distance + min-reduce
//   grid (32 t-tiles, 2 p-tiles, 32 b), 512 threads (16 warps, 4M x 4N)
//   CTA tile: M=128 p, N=256 t, K=1024; ldmatrix fragments,
//   cp.async double-buffered proto phases (4 taps each)
// ---------------------------------------------------------------------------
#define NT_       256
#define FROWS     272
#define ROWB      144
#define SF_BYTES  (FROWS * ROWB)                 // 39168
#define SP_TAP    (128 * ROWB)                   // 18432
#define SP_BYTES  (4 * SP_TAP)                   // 73728
#define GEMM_DYN  (SF_BYTES + 2 * SP_BYTES)      // 186624

__device__ __forceinline__ void mma16816(float* c, const uint32_t* a,
                                         const uint32_t* b)
{
    asm volatile(
        "mma.sync.aligned.m16n8k16.row.col.f32.bf16.bf16.f32 "
        "{%0,%1,%2,%3}, {%4,%5,%6,%7}, {%8,%9}, {%0,%1,%2,%3};"
        : "+f"(c[0]), "+f"(c[1]), "+f"(c[2]), "+f"(c[3])
        : "r"(a[0]), "r"(a[1]), "r"(a[2]), "r"(a[3]), "r"(b[0]), "r"(b[1]));
}
#define LDSM4(r0, r1, r2, r3, addr)                                           \
    asm volatile("ldmatrix.sync.aligned.m8n8.x4.shared.b16 {%0,%1,%2,%3},[%4];" \
        : "=r"(r0), "=r"(r1), "=r"(r2), "=r"(r3) : "r"(addr))

__global__ void __launch_bounds__(512, 1)
gemm_min_kernel(unsigned* __restrict__ md)
{
    extern __shared__ char dynsm[];
    char* sf = dynsm;                       // f tile [272][144B]
    char* sp = dynsm + SF_BYTES;            // protos, double buffer

    __shared__ float    s_g[FROWS];
    __shared__ float    s2s[NT_];
    __shared__ float    s_p2[128];
    __shared__ unsigned s_md[128];

    const int b   = blockIdx.z;
    const int t0  = blockIdx.x * NT_;
    const int p0  = blockIdx.y * 128;
    const int tid = threadIdx.x;
    const int lane = tid & 31;
    const int wid  = tid >> 5;
    const int wm = wid & 3;
    const int wn = wid >> 2;
    const int sub = lane >> 3;
    const int lr  = lane & 7;

    const uint32_t sf_u32 = smem_u32(sf);
    const uint32_t sp_u32 = smem_u32(sp);

    // ---- async load f tile ----
    const __nv_bfloat16* fT = d_fT + (size_t)b * TPAD * LAT;
    for (int i = tid; i < FROWS * 8; i += 512) {
        int r = i >> 3, seg = i & 7;
        cp16(sf_u32 + r * ROWB + seg * 16,
             fT + (size_t)(t0 + r) * LAT + seg * 8);
    }
    // ---- async load proto phase 0 into buffer 0 ----
    for (int i = tid; i < 4096; i += 512) {
        int j = i >> 10, rs = i & 1023;
        int r = rs >> 3, seg = rs & 7;
        cp16(sp_u32 + j * SP_TAP + r * ROWB + seg * 16,
             d_protA + ((size_t)(j * 256 + p0 + r)) * LAT + seg * 8);
    }
    CP_COMMIT();

    for (int i = tid; i < FROWS; i += 512) s_g[i] = d_g[b * TPAD + t0 + i];
    if (tid < 128) {
        s_p2[tid] = d_p2[p0 + tid];
        s_md[tid] = 0x7f800000u;
    }
    CP_WAIT0();
    __syncthreads();

    if (tid < NT_) {
        float s = 0.f;
#pragma unroll
        for (int k = 0; k < KP; k++) s += s_g[tid + k];
        s2s[tid] = s;
    }

    float acc[2][8][4];
#pragma unroll
    for (int mt = 0; mt < 2; mt++)
#pragma unroll
        for (int nt = 0; nt < 8; nt++)
#pragma unroll
            for (int e = 0; e < 4; e++) acc[mt][nt][e] = 0.f;

    // per-thread ldmatrix base offsets
    const uint32_t a_off = (uint32_t)((wm * 32 + (sub & 1) * 8 + lr) * ROWB
                                      + (sub >> 1) * 16);
    const uint32_t b_off = (uint32_t)((wn * 64 + (sub >> 1) * 8 + lr) * ROWB
                                      + (sub & 1) * 16);

    for (int ph = 0; ph < 4; ph++) {
        const uint32_t buf = sp_u32 + (ph & 1) * SP_BYTES;

        if (ph < 3) {   // prefetch next phase into the other buffer
            const uint32_t nbuf = sp_u32 + ((ph + 1) & 1) * SP_BYTES;
            for (int i = tid; i < 4096; i += 512) {
                int j = i >> 10, rs = i & 1023;
                int r = rs >> 3, seg = rs & 7;
                cp16(nbuf + j * SP_TAP + r * ROWB + seg * 16,
                     d_protA + ((size_t)(((ph + 1) * 4 + j) * 256 + p0 + r)) * LAT
                             + seg * 8);
            }
            CP_COMMIT();
        }

#pragma unroll
        for (int j = 0; j < 4; j++) {
            const int kk = ph * 4 + j;
            const uint32_t abase = buf + j * SP_TAP + a_off;
            const uint32_t bbase = sf_u32 + kk * ROWB + b_off;
#pragma unroll
            for (int cc = 0; cc < 4; cc++) {
                uint32_t a[2][4], bf[8][2];
#pragma unroll
                for (int mt = 0; mt < 2; mt++)
                    LDSM4(a[mt][0], a[mt][1], a[mt][2], a[mt][3],
                          abase + mt * (16 * ROWB) + cc * 32);
#pragma unroll
                for (int np = 0; np < 4; np++)
                    LDSM4(bf[2*np][0], bf[2*np][1], bf[2*np+1][0], bf[2*np+1][1],
                          bbase + np * (16 * ROWB) + cc * 32);
#pragma unroll
                for (int mt = 0; mt < 2; mt++)
#pragma unroll
                    for (int nt = 0; nt < 8; nt++)
                        mma16816(acc[mt][nt], a[mt], bf[nt]);
            }
        }

        if (ph < 3) {
            CP_WAIT0();
            __syncthreads();
        }
    }

    // ---- epilogue: dist = relu(s2 - 2*xp + p2), min over t ----
    const int g   = lane >> 2;
    const int tig = lane & 3;
#pragma unroll
    for (int mt = 0; mt < 2; mt++) {
#pragma unroll
        for (int half = 0; half < 2; half++) {
            const int pl = wm * 32 + mt * 16 + g + half * 8;
            const float pp = s_p2[pl];
            float mn = __int_as_float(0x7f800000);
#pragma unroll
            for (int nt = 0; nt < 8; nt++) {
#pragma unroll
                for (int e = 0; e < 2; e++) {
                    const int col = wn * 64 + nt * 8 + tig * 2 + e;
                    if (t0 + col < LO) {
                        float xp = acc[mt][nt][half * 2 + e];
                        float dd = fmaxf(s2s[col] - 2.f * xp + pp, 0.f);
                        mn = fminf(mn, dd);
                    }
                }
            }
            atomicMin(&s_md[pl], __float_as_uint(mn));
        }
    }
    __syncthreads();
    if (tid < 128 && p0 + tid < P_)
        atomicMin(&md[b * P_ + p0 + tid], s_md[tid]);
}

// ---------------------------------------------------------------------------
// Kernel 5: head
// ---------------------------------------------------------------------------
__global__ void head_kernel(const float* __restrict__ lw,
                            float* __restrict__ out)
{
    __shared__ float acts[B_ * P_];
    const unsigned* mdb = (const unsigned*)(out + B_ * C_);
    const int tid = threadIdx.x;
    for (int i = tid; i < B_ * P_; i += 320) {
        float m = __uint_as_float(mdb[i]);
        acts[i] = logf((m + 1.0f) / (m + EPS_));
    }
    __syncthreads();
    if (tid < B_ * C_) {
        int bb = tid / C_, c = tid % C_;
        float s = 0.f;
        for (int pidx = 0; pidx < P_; pidx++)
            s += acts[bb * P_ + pidx] * lw[c * P_ + pidx];
        out[bb * C_ + c] = s;
    }
}

// ---------------------------------------------------------------------------
extern "C" void kernel_launch(void* const* d_in, const int* in_sizes, int n_in,
                              void* d_out, int out_size)
{
    const float* x       = (const float*)d_in[0];
    const float* enc_w   = (const float*)d_in[1];
    const float* addon_w = (const float*)d_in[2];
    const float* protos  = (const float*)d_in[3];
    const float* last_w  = (const float*)d_in[4];
    float* out = (float*)d_out;

    cudaFuncSetAttribute(enc_addon_kernel,
                         cudaFuncAttributeMaxDynamicSharedMemorySize, ENC_DYN);
    cudaFuncSetAttribute(gemm_min_kernel,
                         cudaFuncAttributeMaxDynamicSharedMemorySize, GEMM_DYN);

    unsigned* md = (unsigned*)(out + B_ * C_);

    init_kernel<<<(B_ * P_ + 255) / 256, 256>>>(md);
    p2_kernel<<<P_, 256>>>(protos);
    protA_kernel<<<(16 * 256 * LAT + 255) / 256, 256>>>(protos);
    enc_addon_kernel<<<dim3(32, B_), 256, ENC_DYN>>>(x, enc_w, addon_w);
    gemm_min_kernel<<<dim3(32, 2, B_), 512, GEMM_DYN>>>(md);
    head_kernel<<<1, 320>>>(last_w, out);
}

// round 5
// speedup vs baseline: 7.1211x; 1.0758x over previous
#include <cuda_runtime.h>
#include <cuda_bf16.h>
#include <cstdint>

// ---------------------------------------------------------------------------
// ProtoTSNet on GB300 — round 5
//  - enc: HMMA (split-bf16 hi/lo, 3-pass) for both conv stages
//  - gemm: unchanged from round 4 (ldmatrix + cp.async double buffer)
//
// out[0..319]    = logits [32,10]
// out[320..6719] = min_distances [32,200]
// ---------------------------------------------------------------------------

#define B_     32
#define FIN    16
#define L_     8192
#define LAT    64
#define L1_    8190
#define P_     200
#define KP     16
#define LO     8175
#define C_     10
#define EPS_   1e-4f
#define TPAD   8224

// ---------------- static device scratch (allocation-free) -----------------
__device__ __nv_bfloat16 d_fT[B_ * TPAD * LAT];    // f [b][t][c], bf16
__device__ float         d_g [B_ * TPAD];          // sum_c f_bf16^2
__device__ __nv_bfloat16 d_protA[16 * 256 * LAT];  // protos [kk][p pad256][c]
__device__ float         d_p2[256];                // ||p||^2 (bf16-rounded)
__device__ __nv_bfloat16 d_w1[3 * 64 * 32];        // enc w  [tap][ch][16hi|16lo]
__device__ __nv_bfloat16 d_w2[64 * 128];           // addon w [ch2][64hi|64lo]

__device__ __forceinline__ uint32_t smem_u32(const void* p) {
    uint32_t a;
    asm("{ .reg .u64 t; cvta.to.shared.u64 t, %1; cvt.u32.u64 %0, t; }"
        : "=r"(a) : "l"(p));
    return a;
}
__device__ __forceinline__ void cp16(uint32_t s, const void* g) {
    asm volatile("cp.async.cg.shared.global [%0], [%1], 16;" :: "r"(s), "l"(g));
}
#define CP_COMMIT() asm volatile("cp.async.commit_group;" ::: "memory")
#define CP_WAIT0()  asm volatile("cp.async.wait_group 0;" ::: "memory")

__device__ __forceinline__ void mma16816(float* c, const uint32_t* a,
                                         const uint32_t* b)
{
    asm volatile(
        "mma.sync.aligned.m16n8k16.row.col.f32.bf16.bf16.f32 "
        "{%0,%1,%2,%3}, {%4,%5,%6,%7}, {%8,%9}, {%0,%1,%2,%3};"
        : "+f"(c[0]), "+f"(c[1]), "+f"(c[2]), "+f"(c[3])
        : "r"(a[0]), "r"(a[1]), "r"(a[2]), "r"(a[3]), "r"(b[0]), "r"(b[1]));
}
#define LDSM4(r0, r1, r2, r3, addr)                                           \
    asm volatile("ldmatrix.sync.aligned.m8n8.x4.shared.b16 {%0,%1,%2,%3},[%4];" \
        : "=r"(r0), "=r"(r1), "=r"(r2), "=r"(r3) : "r"(addr))

// ---------------------------------------------------------------------------
// Weight prep: split fp32 weights into bf16 hi/lo planes
// ---------------------------------------------------------------------------
__global__ void prep_w1_kernel(const float* __restrict__ ew)
{
    int idx = blockIdx.x * 256 + threadIdx.x;      // [tap][ch][pos<32]
    if (idx >= 3 * 64 * 32) return;
    int pos = idx & 31, ch = (idx >> 5) & 63, tap = idx >> 11;
    int i = pos & 15;
    float w = ew[ch * 48 + i * 3 + tap];
    __nv_bfloat16 hi = __float2bfloat16(w);
    if (pos < 16) d_w1[idx] = hi;
    else          d_w1[idx] = __float2bfloat16(w - __bfloat162float(hi));
}
__global__ void prep_w2_kernel(const float* __restrict__ aw)
{
    int idx = blockIdx.x * 256 + threadIdx.x;      // [ch2][pos<128]
    if (idx >= 64 * 128) return;
    int pos = idx & 127, ch2 = idx >> 7;
    int c = pos & 63;
    float w = aw[ch2 * 64 + c];
    __nv_bfloat16 hi = __float2bfloat16(w);
    if (pos < 64) d_w2[idx] = hi;
    else          d_w2[idx] = __float2bfloat16(w - __bfloat162float(hi));
}

// ---------------------------------------------------------------------------
// Kernel 1: enc conv(k=3)+ReLU + addon 1x1+ReLU via HMMA, split-bf16 3-pass
//   grid (32 t-tiles, B), 256 threads (8 warps: 4 t-quarters x 2 ch-halves)
//   M = t (256), N = ch (64)
// ---------------------------------------------------------------------------
#define B1_ROWB 80
#define OFF_B1  0                       // x tile   [260][80B]  (16hi|16lo bf16)
#define OFF_A1  20800                   // w1       [3][64][80B]
#define OFF_A2  36160                   // w2       [64][272B]
#define OFF_B2  53568                   // f1 tile  [256][272B] (64hi|64lo bf16)
#define ENC_DYN 123200

__global__ void __launch_bounds__(256, 1)
enc_addon_kernel(const float* __restrict__ x)
{
    extern __shared__ char esm[];
    __shared__ float s_g2[256];

    const int b   = blockIdx.y;
    const int t0  = blockIdx.x * 256;
    const int tid = threadIdx.x;
    const int lane = tid & 31;
    const int wid  = tid >> 5;
    const int wm  = wid & 3;        // t quarter (64 t)
    const int wn  = wid >> 2;       // ch half (32 ch)
    const int sub = lane >> 3;
    const int lr  = lane & 7;
    const int g   = lane >> 2;
    const int tig = lane & 3;

    const uint32_t b1_u = smem_u32(esm) + OFF_B1;
    const uint32_t a1_u = smem_u32(esm) + OFF_A1;
    const uint32_t a2_u = smem_u32(esm) + OFF_A2;
    const uint32_t b2_u = smem_u32(esm) + OFF_B2;

    // ---- load + split x tile: [260 rows][16hi|16lo] ----
    for (int idx = tid; idx < 16 * 260; idx += 256) {
        int i = idx / 260, r = idx - i * 260;
        int t = t0 + r;
        float v = (t < L_ && r < 258) ? x[(b * FIN + i) * L_ + t] : 0.f;
        __nv_bfloat16 hi = __float2bfloat16(v);
        __nv_bfloat16 lo = __float2bfloat16(v - __bfloat162float(hi));
        char* row = esm + OFF_B1 + r * B1_ROWB;
        *reinterpret_cast<__nv_bfloat16*>(row + i * 2)      = hi;
        *reinterpret_cast<__nv_bfloat16*>(row + 32 + i * 2) = lo;
    }
    // ---- w1 -> smem [tap][64][80B] ----
    for (int idx = tid; idx < 3 * 64 * 16; idx += 256) {
        int q = idx & 15, ch = (idx >> 4) & 63, tap = idx >> 10;
        *reinterpret_cast<uint32_t*>(esm + OFF_A1 + tap * (64 * B1_ROWB)
                                     + ch * B1_ROWB + q * 4) =
            reinterpret_cast<const uint32_t*>(d_w1)[idx];
    }
    // ---- w2 -> smem [64][272B] ----
    for (int idx = tid; idx < 64 * 64; idx += 256) {
        int q = idx & 63, ch2 = idx >> 6;
        *reinterpret_cast<uint32_t*>(esm + OFF_A2 + ch2 * 272 + q * 4) =
            reinterpret_cast<const uint32_t*>(d_w2)[idx];
    }
    if (tid < 256) s_g2[tid] = 0.f;
    __syncthreads();

    // ================= stage 1: conv k=3 =================
    float acc1[4][4][4];
#pragma unroll
    for (int mt = 0; mt < 4; mt++)
#pragma unroll
        for (int nt = 0; nt < 4; nt++)
#pragma unroll
            for (int e = 0; e < 4; e++) acc1[mt][nt][e] = 0.f;

    const uint32_t a1row = (uint32_t)(wm * 64 + (sub & 1) * 8 + lr);
    const uint32_t a1colq = (uint32_t)((sub >> 1) * 16);
    const uint32_t w1row = (uint32_t)((wn * 32 + (sub >> 1) * 8 + lr) * B1_ROWB
                                      + (sub & 1) * 16);

#pragma unroll
    for (int tap = 0; tap < 3; tap++) {
#pragma unroll
        for (int pass = 0; pass < 3; pass++) {
            const uint32_t colA = (pass == 2) ? 32u : 0u;  // x lo on pass 2
            const uint32_t colB = (pass == 1) ? 32u : 0u;  // w lo on pass 1
            uint32_t bf[4][2];
            const uint32_t wb = a1_u + tap * (64 * B1_ROWB) + w1row + colB;
            LDSM4(bf[0][0], bf[0][1], bf[1][0], bf[1][1], wb);
            LDSM4(bf[2][0], bf[2][1], bf[3][0], bf[3][1], wb + 16 * B1_ROWB);
#pragma unroll
            for (int mt = 0; mt < 4; mt++) {
                uint32_t a[4];
                LDSM4(a[0], a[1], a[2], a[3],
                      b1_u + (a1row + mt * 16 + tap) * B1_ROWB + a1colq + colA);
#pragma unroll
                for (int nt = 0; nt < 4; nt++)
                    mma16816(acc1[mt][nt], a, bf[nt]);
            }
        }
    }

    // ---- epilogue 1: relu, split hi/lo, store f1 -> B2 [t][64hi|64lo] ----
#pragma unroll
    for (int mt = 0; mt < 4; mt++) {
#pragma unroll
        for (int nt = 0; nt < 4; nt++) {
#pragma unroll
            for (int eh = 0; eh < 2; eh++) {
                const int t  = wm * 64 + mt * 16 + g + eh * 8;
                const int ch = wn * 32 + nt * 8 + tig * 2;
                float v0 = fmaxf(acc1[mt][nt][eh * 2 + 0], 0.f);
                float v1 = fmaxf(acc1[mt][nt][eh * 2 + 1], 0.f);
                __nv_bfloat16 h0 = __float2bfloat16(v0);
                __nv_bfloat16 h1 = __float2bfloat16(v1);
                __nv_bfloat16 l0 = __float2bfloat16(v0 - __bfloat162float(h0));
                __nv_bfloat16 l1 = __float2bfloat16(v1 - __bfloat162float(h1));
                uint32_t hp = (uint32_t)__bfloat16_as_ushort(h0)
                            | ((uint32_t)__bfloat16_as_ushort(h1) << 16);
                uint32_t lp = (uint32_t)__bfloat16_as_ushort(l0)
                            | ((uint32_t)__bfloat16_as_ushort(l1) << 16);
                char* row = esm + OFF_B2 + t * 272;
                *reinterpret_cast<uint32_t*>(row + ch * 2)       = hp;
                *reinterpret_cast<uint32_t*>(row + 128 + ch * 2) = lp;
            }
        }
    }
    __syncthreads();

    // ================= stage 2: 1x1 addon =================
    float acc2[4][4][4];
#pragma unroll
    for (int mt = 0; mt < 4; mt++)
#pragma unroll
        for (int nt = 0; nt < 4; nt++)
#pragma unroll
            for (int e = 0; e < 4; e++) acc2[mt][nt][e] = 0.f;

    const uint32_t a2base = b2_u + (uint32_t)((wm * 64 + (sub & 1) * 8 + lr) * 272
                                              + (sub >> 1) * 16);
    const uint32_t w2base = a2_u + (uint32_t)((wn * 32 + (sub >> 1) * 8 + lr) * 272
                                              + (sub & 1) * 16);

#pragma unroll
    for (int step = 0; step < 12; step++) {
        const int kc   = step & 3;
        const int pass = step >> 2;            // 0: hh, 1: h·lo(w), 2: lo(f)·h
        const uint32_t colA = (pass == 2) ? (128u + kc * 32u) : (kc * 32u);
        const uint32_t colB = (pass == 1) ? (128u + kc * 32u) : (kc * 32u);
        uint32_t bf[4][2];
        LDSM4(bf[0][0], bf[0][1], bf[1][0], bf[1][1], w2base + colB);
        LDSM4(bf[2][0], bf[2][1], bf[3][0], bf[3][1], w2base + colB + 16 * 272);
#pragma unroll
        for (int mt = 0; mt < 4; mt++) {
            uint32_t a[4];
            LDSM4(a[0], a[1], a[2], a[3], a2base + mt * (16 * 272) + colA);
#pragma unroll
            for (int nt = 0; nt < 4; nt++)
                mma16816(acc2[mt][nt], a, bf[nt]);
        }
    }

    // ---- epilogue 2: relu, round bf16, store f, accumulate g ----
#pragma unroll
    for (int mt = 0; mt < 4; mt++) {
#pragma unroll
        for (int eh = 0; eh < 2; eh++) {
            const int t  = wm * 64 + mt * 16 + g + eh * 8;
            const int tg = t0 + t;
            float gp = 0.f;
#pragma unroll
            for (int nt = 0; nt < 4; nt++) {
                const int ch = wn * 32 + nt * 8 + tig * 2;
                float v0 = fmaxf(acc2[mt][nt][eh * 2 + 0], 0.f);
                float v1 = fmaxf(acc2[mt][nt][eh * 2 + 1], 0.f);
                __nv_bfloat162 h2 = __floats2bfloat162_rn(v0, v1);
                float r0 = __bfloat162float(__low2bfloat16(h2));
                float r1 = __bfloat162float(__high2bfloat16(h2));
                gp += r0 * r0 + r1 * r1;
                if (tg < L1_)
                    *reinterpret_cast<uint32_t*>(
                        d_fT + ((size_t)b * TPAD + tg) * LAT + ch) =
                        *reinterpret_cast<uint32_t*>(&h2);
            }
            atomicAdd(&s_g2[t], gp);
        }
    }
    __syncthreads();
    if (t0 + tid < L1_) d_g[b * TPAD + t0 + tid] = s_g2[tid];
}

// ---------------------------------------------------------------------------
// Kernel 2: rearrange protos -> d_protA [kk][p pad256][c], bf16
// ---------------------------------------------------------------------------
__global__ void protA_kernel(const float* __restrict__ protos)
{
    int idx = blockIdx.x * 256 + threadIdx.x;
    if (idx >= 16 * 256 * LAT) return;
    int c  = idx & 63;
    int pp = (idx >> 6) & 255;
    int kk = idx >> 14;
    float v = (pp < P_) ? protos[pp * (LAT * KP) + c * KP + kk] : 0.f;
    d_protA[idx] = __float2bfloat16(v);
}

// ---------------------------------------------------------------------------
// Kernel 3: p2 from bf16-rounded protos
// ---------------------------------------------------------------------------
__global__ void p2_kernel(const float* __restrict__ protos)
{
    const int p = blockIdx.x;
    const int tid = threadIdx.x;
    float s = 0.f;
    for (int i = tid; i < LAT * KP; i += 256) {
        float v = __bfloat162float(__float2bfloat16(protos[p * LAT * KP + i]));
        s += v * v;
    }
#pragma unroll
    for (int o = 16; o; o >>= 1) s += __shfl_xor_sync(0xffffffffu, s, o);
    __shared__ float red[8];
    if ((tid & 31) == 0) red[tid >> 5] = s;
    __syncthreads();
    if (tid == 0) {
        float ts = 0.f;
        for (int w = 0; w < 8; w++) ts += red[w];
        d_p2[p] = ts;
    }
}

__global__ void init_kernel(unsigned* __restrict__ md)
{
    int i = blockIdx.x * 256 + threadIdx.x;
    if (i < B_ * P_) md[i] = 0x7f800000u;
}

// ---------------------------------------------------------------------------
// Kernel 4: HMMA GEMM + distance + min-reduce (unchanged from round 4)
// ---------------------------------------------------------------------------
#define NT_       256
#define FROWS     272
#define ROWB      144
#define SF_BYTES  (FROWS * ROWB)
#define SP_TAP    (128 * ROWB)
#define SP_BYTES  (4 * SP_TAP)
#define GEMM_DYN  (SF_BYTES + 2 * SP_BYTES)

__global__ void __launch_bounds__(512, 1)
gemm_min_kernel(unsigned* __restrict__ md)
{
    extern __shared__ char dynsm[];
    char* sf = dynsm;
    char* sp = dynsm + SF_BYTES;

    __shared__ float    s_g[FROWS];
    __shared__ float    s2s[NT_];
    __shared__ float    s_p2[128];
    __shared__ unsigned s_md[128];

    const int b   = blockIdx.z;
    const int t0  = blockIdx.x * NT_;
    const int p0  = blockIdx.y * 128;
    const int tid = threadIdx.x;
    const int lane = tid & 31;
    const int wid  = tid >> 5;
    const int wm = wid & 3;
    const int wn = wid >> 2;
    const int sub = lane >> 3;
    const int lr  = lane & 7;

    const uint32_t sf_u32 = smem_u32(sf);
    const uint32_t sp_u32 = smem_u32(sp);

    const __nv_bfloat16* fT = d_fT + (size_t)b * TPAD * LAT;
    for (int i = tid; i < FROWS * 8; i += 512) {
        int r = i >> 3, seg = i & 7;
        cp16(sf_u32 + r * ROWB + seg * 16,
             fT + (size_t)(t0 + r) * LAT + seg * 8);
    }
    for (int i = tid; i < 4096; i += 512) {
        int j = i >> 10, rs = i & 1023;
        int r = rs >> 3, seg = rs & 7;
        cp16(sp_u32 + j * SP_TAP + r * ROWB + seg * 16,
             d_protA + ((size_t)(j * 256 + p0 + r)) * LAT + seg * 8);
    }
    CP_COMMIT();

    for (int i = tid; i < FROWS; i += 512) s_g[i] = d_g[b * TPAD + t0 + i];
    if (tid < 128) {
        s_p2[tid] = d_p2[p0 + tid];
        s_md[tid] = 0x7f800000u;
    }
    CP_WAIT0();
    __syncthreads();

    if (tid < NT_) {
        float s = 0.f;
#pragma unroll
        for (int k = 0; k < KP; k++) s += s_g[tid + k];
        s2s[tid] = s;
    }

    float acc[2][8][4];
#pragma unroll
    for (int mt = 0; mt < 2; mt++)
#pragma unroll
        for (int nt = 0; nt < 8; nt++)
#pragma unroll
            for (int e = 0; e < 4; e++) acc[mt][nt][e] = 0.f;

    const uint32_t a_off = (uint32_t)((wm * 32 + (sub & 1) * 8 + lr) * ROWB
                                      + (sub >> 1) * 16);
    const uint32_t b_off = (uint32_t)((wn * 64 + (sub >> 1) * 8 + lr) * ROWB
                                      + (sub & 1) * 16);

    for (int ph = 0; ph < 4; ph++) {
        const uint32_t buf = sp_u32 + (ph & 1) * SP_BYTES;

        if (ph < 3) {
            const uint32_t nbuf = sp_u32 + ((ph + 1) & 1) * SP_BYTES;
            for (int i = tid; i < 4096; i += 512) {
                int j = i >> 10, rs = i & 1023;
                int r = rs >> 3, seg = rs & 7;
                cp16(nbuf + j * SP_TAP + r * ROWB + seg * 16,
                     d_protA + ((size_t)(((ph + 1) * 4 + j) * 256 + p0 + r)) * LAT
                             + seg * 8);
            }
            CP_COMMIT();
        }

#pragma unroll
        for (int j = 0; j < 4; j++) {
            const int kk = ph * 4 + j;
            const uint32_t abase = buf + j * SP_TAP + a_off;
            const uint32_t bbase = sf_u32 + kk * ROWB + b_off;
#pragma unroll
            for (int cc = 0; cc < 4; cc++) {
                uint32_t a[2][4], bf[8][2];
#pragma unroll
                for (int mt = 0; mt < 2; mt++)
                    LDSM4(a[mt][0], a[mt][1], a[mt][2], a[mt][3],
                          abase + mt * (16 * ROWB) + cc * 32);
#pragma unroll
                for (int np = 0; np < 4; np++)
                    LDSM4(bf[2*np][0], bf[2*np][1], bf[2*np+1][0], bf[2*np+1][1],
                          bbase + np * (16 * ROWB) + cc * 32);
#pragma unroll
                for (int mt = 0; mt < 2; mt++)
#pragma unroll
                    for (int nt = 0; nt < 8; nt++)
                        mma16816(acc[mt][nt], a[mt], bf[nt]);
            }
        }

        if (ph < 3) {
            CP_WAIT0();
            __syncthreads();
        }
    }

    const int g   = lane >> 2;
    const int tig = lane & 3;
#pragma unroll
    for (int mt = 0; mt < 2; mt++) {
#pragma unroll
        for (int half = 0; half < 2; half++) {
            const int pl = wm * 32 + mt * 16 + g + half * 8;
            const float pp = s_p2[pl];
            float mn = __int_as_float(0x7f800000);
#pragma unroll
            for (int nt = 0; nt < 8; nt++) {
#pragma unroll
                for (int e = 0; e < 2; e++) {
                    const int col = wn * 64 + nt * 8 + tig * 2 + e;
                    if (t0 + col < LO) {
                        float xp = acc[mt][nt][half * 2 + e];
                        float dd = fmaxf(s2s[col] - 2.f * xp + pp, 0.f);
                        mn = fminf(mn, dd);
                    }
                }
            }
            atomicMin(&s_md[pl], __float_as_uint(mn));
        }
    }
    __syncthreads();
    if (tid < 128 && p0 + tid < P_)
        atomicMin(&md[b * P_ + p0 + tid], s_md[tid]);
}

// ---------------------------------------------------------------------------
// Kernel 5: head
// ---------------------------------------------------------------------------
__global__ void head_kernel(const float* __restrict__ lw,
                            float* __restrict__ out)
{
    __shared__ float acts[B_ * P_];
    const unsigned* mdb = (const unsigned*)(out + B_ * C_);
    const int tid = threadIdx.x;
    for (int i = tid; i < B_ * P_; i += 320) {
        float m = __uint_as_float(mdb[i]);
        acts[i] = logf((m + 1.0f) / (m + EPS_));
    }
    __syncthreads();
    if (tid < B_ * C_) {
        int bb = tid / C_, c = tid % C_;
        float s = 0.f;
        for (int pidx = 0; pidx < P_; pidx++)
            s += acts[bb * P_ + pidx] * lw[c * P_ + pidx];
        out[bb * C_ + c] = s;
    }
}

// ---------------------------------------------------------------------------
extern "C" void kernel_launch(void* const* d_in, const int* in_sizes, int n_in,
                              void* d_out, int out_size)
{
    const float* x       = (const float*)d_in[0];
    const float* enc_w   = (const float*)d_in[1];
    const float* addon_w = (const float*)d_in[2];
    const float* protos  = (const float*)d_in[3];
    const float* last_w  = (const float*)d_in[4];
    float* out = (float*)d_out;

    cudaFuncSetAttribute(enc_addon_kernel,
                         cudaFuncAttributeMaxDynamicSharedMemorySize, ENC_DYN);
    cudaFuncSetAttribute(gemm_min_kernel,
                         cudaFuncAttributeMaxDynamicSharedMemorySize, GEMM_DYN);

    unsigned* md = (unsigned*)(out + B_ * C_);

    init_kernel<<<(B_ * P_ + 255) / 256, 256>>>(md);
    p2_kernel<<<P_, 256>>>(protos);
    protA_kernel<<<(16 * 256 * LAT + 255) / 256, 256>>>(protos);
    prep_w1_kernel<<<(3 * 64 * 32 + 255) / 256, 256>>>(enc_w);
    prep_w2_kernel<<<(64 * 128 + 255) / 256, 256>>>(addon_w);
    enc_addon_kernel<<<dim3(32, B_), 256, ENC_DYN>>>(x);
    gemm_min_kernel<<<dim3(32, 2, B_), 512, GEMM_DYN>>>(md);
    head_kernel<<<1, 320>>>(last_w, out);
}

// round 7
// speedup vs baseline: 7.1720x; 1.0072x over previous
#include <cuda_runtime.h>
#include <cuda_bf16.h>
#include <cstdint>

// ---------------------------------------------------------------------------
// ProtoTSNet on GB300 — round 7 (round 6 + syntax fix in gemm A-fragment loop)
//  - gemm: 8 warps, 64x64 warp tiles (LDSM traffic -33%)
//  - all prep work merged into a single launch
//
// out[0..319]    = logits [32,10]
// out[320..6719] = min_distances [32,200]
// ---------------------------------------------------------------------------

#define B_     32
#define FIN    16
#define L_     8192
#define LAT    64
#define L1_    8190
#define P_     200
#define KP     16
#define LO     8175
#define C_     10
#define EPS_   1e-4f
#define TPAD   8224

// ---------------- static device scratch (allocation-free) -----------------
__device__ __nv_bfloat16 d_fT[B_ * TPAD * LAT];    // f [b][t][c], bf16
__device__ float         d_g [B_ * TPAD];          // sum_c f_bf16^2
__device__ __nv_bfloat16 d_protA[16 * 256 * LAT];  // protos [kk][p pad256][c]
__device__ float         d_p2[256];                // ||p||^2 (bf16-rounded)
__device__ __nv_bfloat16 d_w1[3 * 64 * 32];        // enc w  [tap][ch][16hi|16lo]
__device__ __nv_bfloat16 d_w2[64 * 128];           // addon w [ch2][64hi|64lo]

__device__ __forceinline__ uint32_t smem_u32(const void* p) {
    uint32_t a;
    asm("{ .reg .u64 t; cvta.to.shared.u64 t, %1; cvt.u32.u64 %0, t; }"
        : "=r"(a) : "l"(p));
    return a;
}
__device__ __forceinline__ void cp16(uint32_t s, const void* g) {
    asm volatile("cp.async.cg.shared.global [%0], [%1], 16;" :: "r"(s), "l"(g));
}
#define CP_COMMIT() asm volatile("cp.async.commit_group;" ::: "memory")
#define CP_WAIT0()  asm volatile("cp.async.wait_group 0;" ::: "memory")

__device__ __forceinline__ void mma16816(float* c, const uint32_t* a,
                                         const uint32_t* b)
{
    asm volatile(
        "mma.sync.aligned.m16n8k16.row.col.f32.bf16.bf16.f32 "
        "{%0,%1,%2,%3}, {%4,%5,%6,%7}, {%8,%9}, {%0,%1,%2,%3};"
        : "+f"(c[0]), "+f"(c[1]), "+f"(c[2]), "+f"(c[3])
        : "r"(a[0]), "r"(a[1]), "r"(a[2]), "r"(a[3]), "r"(b[0]), "r"(b[1]));
}
#define LDSM4(r0, r1, r2, r3, addr)                                           \
    asm volatile("ldmatrix.sync.aligned.m8n8.x4.shared.b16 {%0,%1,%2,%3},[%4];" \
        : "=r"(r0), "=r"(r1), "=r"(r2), "=r"(r3) : "r"(addr))

// ---------------------------------------------------------------------------
// Kernel 0: merged prep (block-range dispatch)
// ---------------------------------------------------------------------------
#define PREP_GRID 1305

__global__ void prep_kernel(const float* __restrict__ protos,
                            const float* __restrict__ ew,
                            const float* __restrict__ aw,
                            unsigned* __restrict__ md)
{
    const int blk = blockIdx.x;
    const int tid = threadIdx.x;

    if (blk < 1024) {                              // protA
        int idx = blk * 256 + tid;
        int c  = idx & 63;
        int pp = (idx >> 6) & 255;
        int kk = idx >> 14;
        float v = (pp < P_) ? protos[pp * (LAT * KP) + c * KP + kk] : 0.f;
        d_protA[idx] = __float2bfloat16(v);
    } else if (blk < 1224) {                       // p2
        const int p = blk - 1024;
        float s = 0.f;
        for (int i = tid; i < LAT * KP; i += 256) {
            float v = __bfloat162float(__float2bfloat16(protos[p * LAT * KP + i]));
            s += v * v;
        }
#pragma unroll
        for (int o = 16; o; o >>= 1) s += __shfl_xor_sync(0xffffffffu, s, o);
        __shared__ float red[8];
        if ((tid & 31) == 0) red[tid >> 5] = s;
        __syncthreads();
        if (tid == 0) {
            float ts = 0.f;
            for (int w = 0; w < 8; w++) ts += red[w];
            d_p2[p] = ts;
        }
    } else if (blk < 1249) {                       // init md
        int i = (blk - 1224) * 256 + tid;
        if (i < B_ * P_) md[i] = 0x7f800000u;
    } else if (blk < 1273) {                       // prep_w1
        int idx = (blk - 1249) * 256 + tid;
        if (idx < 3 * 64 * 32) {
            int pos = idx & 31, ch = (idx >> 5) & 63, tap = idx >> 11;
            int i = pos & 15;
            float w = ew[ch * 48 + i * 3 + tap];
            __nv_bfloat16 hi = __float2bfloat16(w);
            if (pos < 16) d_w1[idx] = hi;
            else          d_w1[idx] = __float2bfloat16(w - __bfloat162float(hi));
        }
    } else {                                       // prep_w2
        int idx = (blk - 1273) * 256 + tid;
        if (idx < 64 * 128) {
            int pos = idx & 127, ch2 = idx >> 7;
            int c = pos & 63;
            float w = aw[ch2 * 64 + c];
            __nv_bfloat16 hi = __float2bfloat16(w);
            if (pos < 64) d_w2[idx] = hi;
            else          d_w2[idx] = __float2bfloat16(w - __bfloat162float(hi));
        }
    }
}

// ---------------------------------------------------------------------------
// Kernel 1: enc conv(k=3)+ReLU + addon 1x1+ReLU via HMMA, split-bf16 3-pass
//   grid (32 t-tiles, B), 256 threads (8 warps: 4 t-quarters x 2 ch-halves)
// ---------------------------------------------------------------------------
#define B1_ROWB 80
#define OFF_B1  0
#define OFF_A1  20800
#define OFF_A2  36160
#define OFF_B2  53568
#define ENC_DYN 123200

__global__ void __launch_bounds__(256, 1)
enc_addon_kernel(const float* __restrict__ x)
{
    extern __shared__ char esm[];
    __shared__ float s_g2[256];

    const int b   = blockIdx.y;
    const int t0  = blockIdx.x * 256;
    const int tid = threadIdx.x;
    const int lane = tid & 31;
    const int wid  = tid >> 5;
    const int wm  = wid & 3;
    const int wn  = wid >> 2;
    const int sub = lane >> 3;
    const int lr  = lane & 7;
    const int g   = lane >> 2;
    const int tig = lane & 3;

    const uint32_t b1_u = smem_u32(esm) + OFF_B1;
    const uint32_t a1_u = smem_u32(esm) + OFF_A1;
    const uint32_t a2_u = smem_u32(esm) + OFF_A2;
    const uint32_t b2_u = smem_u32(esm) + OFF_B2;

    for (int idx = tid; idx < 16 * 260; idx += 256) {
        int i = idx / 260, r = idx - i * 260;
        int t = t0 + r;
        float v = (t < L_ && r < 258) ? x[(b * FIN + i) * L_ + t] : 0.f;
        __nv_bfloat16 hi = __float2bfloat16(v);
        __nv_bfloat16 lo = __float2bfloat16(v - __bfloat162float(hi));
        char* row = esm + OFF_B1 + r * B1_ROWB;
        *reinterpret_cast<__nv_bfloat16*>(row + i * 2)      = hi;
        *reinterpret_cast<__nv_bfloat16*>(row + 32 + i * 2) = lo;
    }
    for (int idx = tid; idx < 3 * 64 * 16; idx += 256) {
        int q = idx & 15, ch = (idx >> 4) & 63, tap = idx >> 10;
        *reinterpret_cast<uint32_t*>(esm + OFF_A1 + tap * (64 * B1_ROWB)
                                     + ch * B1_ROWB + q * 4) =
            reinterpret_cast<const uint32_t*>(d_w1)[idx];
    }
    for (int idx = tid; idx < 64 * 64; idx += 256) {
        int q = idx & 63, ch2 = idx >> 6;
        *reinterpret_cast<uint32_t*>(esm + OFF_A2 + ch2 * 272 + q * 4) =
            reinterpret_cast<const uint32_t*>(d_w2)[idx];
    }
    if (tid < 256) s_g2[tid] = 0.f;
    __syncthreads();

    // ---- stage 1: conv k=3 ----
    float acc1[4][4][4];
#pragma unroll
    for (int mt = 0; mt < 4; mt++)
#pragma unroll
        for (int nt = 0; nt < 4; nt++)
#pragma unroll
            for (int e = 0; e < 4; e++) acc1[mt][nt][e] = 0.f;

    const uint32_t a1row = (uint32_t)(wm * 64 + (sub & 1) * 8 + lr);
    const uint32_t a1colq = (uint32_t)((sub >> 1) * 16);
    const uint32_t w1row = (uint32_t)((wn * 32 + (sub >> 1) * 8 + lr) * B1_ROWB
                                      + (sub & 1) * 16);

#pragma unroll
    for (int tap = 0; tap < 3; tap++) {
#pragma unroll
        for (int pass = 0; pass < 3; pass++) {
            const uint32_t colA = (pass == 2) ? 32u : 0u;
            const uint32_t colB = (pass == 1) ? 32u : 0u;
            uint32_t bf[4][2];
            const uint32_t wb = a1_u + tap * (64 * B1_ROWB) + w1row + colB;
            LDSM4(bf[0][0], bf[0][1], bf[1][0], bf[1][1], wb);
            LDSM4(bf[2][0], bf[2][1], bf[3][0], bf[3][1], wb + 16 * B1_ROWB);
#pragma unroll
            for (int mt = 0; mt < 4; mt++) {
                uint32_t a[4];
                LDSM4(a[0], a[1], a[2], a[3],
                      b1_u + (a1row + mt * 16 + tap) * B1_ROWB + a1colq + colA);
#pragma unroll
                for (int nt = 0; nt < 4; nt++)
                    mma16816(acc1[mt][nt], a, bf[nt]);
            }
        }
    }

    // ---- epilogue 1 ----
#pragma unroll
    for (int mt = 0; mt < 4; mt++) {
#pragma unroll
        for (int nt = 0; nt < 4; nt++) {
#pragma unroll
            for (int eh = 0; eh < 2; eh++) {
                const int t  = wm * 64 + mt * 16 + g + eh * 8;
                const int ch = wn * 32 + nt * 8 + tig * 2;
                float v0 = fmaxf(acc1[mt][nt][eh * 2 + 0], 0.f);
                float v1 = fmaxf(acc1[mt][nt][eh * 2 + 1], 0.f);
                __nv_bfloat16 h0 = __float2bfloat16(v0);
                __nv_bfloat16 h1 = __float2bfloat16(v1);
                __nv_bfloat16 l0 = __float2bfloat16(v0 - __bfloat162float(h0));
                __nv_bfloat16 l1 = __float2bfloat16(v1 - __bfloat162float(h1));
                uint32_t hp = (uint32_t)__bfloat16_as_ushort(h0)
                            | ((uint32_t)__bfloat16_as_ushort(h1) << 16);
                uint32_t lp = (uint32_t)__bfloat16_as_ushort(l0)
                            | ((uint32_t)__bfloat16_as_ushort(l1) << 16);
                char* row = esm + OFF_B2 + t * 272;
                *reinterpret_cast<uint32_t*>(row + ch * 2)       = hp;
                *reinterpret_cast<uint32_t*>(row + 128 + ch * 2) = lp;
            }
        }
    }
    __syncthreads();

    // ---- stage 2: 1x1 addon ----
    float acc2[4][4][4];
#pragma unroll
    for (int mt = 0; mt < 4; mt++)
#pragma unroll
        for (int nt = 0; nt < 4; nt++)
#pragma unroll
            for (int e = 0; e < 4; e++) acc2[mt][nt][e] = 0.f;

    const uint32_t a2base = b2_u + (uint32_t)((wm * 64 + (sub & 1) * 8 + lr) * 272
                                              + (sub >> 1) * 16);
    const uint32_t w2base = a2_u + (uint32_t)((wn * 32 + (sub >> 1) * 8 + lr) * 272
                                              + (sub & 1) * 16);

#pragma unroll
    for (int step = 0; step < 12; step++) {
        const int kc   = step & 3;
        const int pass = step >> 2;
        const uint32_t colA = (pass == 2) ? (128u + kc * 32u) : (kc * 32u);
        const uint32_t colB = (pass == 1) ? (128u + kc * 32u) : (kc * 32u);
        uint32_t bf[4][2];
        LDSM4(bf[0][0], bf[0][1], bf[1][0], bf[1][1], w2base + colB);
        LDSM4(bf[2][0], bf[2][1], bf[3][0], bf[3][1], w2base + colB + 16 * 272);
#pragma unroll
        for (int mt = 0; mt < 4; mt++) {
            uint32_t a[4];
            LDSM4(a[0], a[1], a[2], a[3], a2base + mt * (16 * 272) + colA);
#pragma unroll
            for (int nt = 0; nt < 4; nt++)
                mma16816(acc2[mt][nt], a, bf[nt]);
        }
    }

    // ---- epilogue 2 ----
#pragma unroll
    for (int mt = 0; mt < 4; mt++) {
#pragma unroll
        for (int eh = 0; eh < 2; eh++) {
            const int t  = wm * 64 + mt * 16 + g + eh * 8;
            const int tg = t0 + t;
            float gp = 0.f;
#pragma unroll
            for (int nt = 0; nt < 4; nt++) {
                const int ch = wn * 32 + nt * 8 + tig * 2;
                float v0 = fmaxf(acc2[mt][nt][eh * 2 + 0], 0.f);
                float v1 = fmaxf(acc2[mt][nt][eh * 2 + 1], 0.f);
                __nv_bfloat162 h2 = __floats2bfloat162_rn(v0, v1);
                float r0 = __bfloat162float(__low2bfloat16(h2));
                float r1 = __bfloat162float(__high2bfloat16(h2));
                gp += r0 * r0 + r1 * r1;
                if (tg < L1_)
                    *reinterpret_cast<uint32_t*>(
                        d_fT + ((size_t)b * TPAD + tg) * LAT + ch) =
                        *reinterpret_cast<uint32_t*>(&h2);
            }
            atomicAdd(&s_g2[t], gp);
        }
    }
    __syncthreads();
    if (t0 + tid < L1_) d_g[b * TPAD + t0 + tid] = s_g2[tid];
}

// ---------------------------------------------------------------------------
// Kernel 2: HMMA GEMM + distance + min-reduce
//   256 threads, 8 warps (2 wm x 4 wn), warp tile 64x64
// ---------------------------------------------------------------------------
#define NT_       256
#define FROWS     272
#define ROWB      144
#define SF_BYTES  (FROWS * ROWB)
#define SP_TAP    (128 * ROWB)
#define SP_BYTES  (4 * SP_TAP)
#define GEMM_DYN  (SF_BYTES + 2 * SP_BYTES)

__global__ void __launch_bounds__(256, 1)
gemm_min_kernel(unsigned* __restrict__ md)
{
    extern __shared__ char dynsm[];
    char* sf = dynsm;
    char* sp = dynsm + SF_BYTES;

    __shared__ float    s_g[FROWS];
    __shared__ float    s2s[NT_];
    __shared__ float    s_p2[128];
    __shared__ unsigned s_md[128];

    const int b   = blockIdx.z;
    const int t0  = blockIdx.x * NT_;
    const int p0  = blockIdx.y * 128;
    const int tid = threadIdx.x;
    const int lane = tid & 31;
    const int wid  = tid >> 5;
    const int wm = wid & 1;          // 64-row M block
    const int wn = wid >> 1;         // 64-col N block
    const int sub = lane >> 3;
    const int lr  = lane & 7;

    const uint32_t sf_u32 = smem_u32(sf);
    const uint32_t sp_u32 = smem_u32(sp);

    const __nv_bfloat16* fT = d_fT + (size_t)b * TPAD * LAT;
    for (int i = tid; i < FROWS * 8; i += 256) {
        int r = i >> 3, seg = i & 7;
        cp16(sf_u32 + r * ROWB + seg * 16,
             fT + (size_t)(t0 + r) * LAT + seg * 8);
    }
    for (int i = tid; i < 4096; i += 256) {
        int j = i >> 10, rs = i & 1023;
        int r = rs >> 3, seg = rs & 7;
        cp16(sp_u32 + j * SP_TAP + r * ROWB + seg * 16,
             d_protA + ((size_t)(j * 256 + p0 + r)) * LAT + seg * 8);
    }
    CP_COMMIT();

    for (int i = tid; i < FROWS; i += 256) s_g[i] = d_g[b * TPAD + t0 + i];
    if (tid < 128) {
        s_p2[tid] = d_p2[p0 + tid];
        s_md[tid] = 0x7f800000u;
    }
    CP_WAIT0();
    __syncthreads();

    if (tid < NT_) {
        float s = 0.f;
#pragma unroll
        for (int k = 0; k < KP; k++) s += s_g[tid + k];
        s2s[tid] = s;
    }

    float acc[4][8][4];
#pragma unroll
    for (int mt = 0; mt < 4; mt++)
#pragma unroll
        for (int nt = 0; nt < 8; nt++)
#pragma unroll
            for (int e = 0; e < 4; e++) acc[mt][nt][e] = 0.f;

    const uint32_t a_off = (uint32_t)((wm * 64 + (sub & 1) * 8 + lr) * ROWB
                                      + (sub >> 1) * 16);
    const uint32_t b_off = (uint32_t)((wn * 64 + (sub >> 1) * 8 + lr) * ROWB
                                      + (sub & 1) * 16);

    for (int ph = 0; ph < 4; ph++) {
        const uint32_t buf = sp_u32 + (ph & 1) * SP_BYTES;

        if (ph < 3) {
            const uint32_t nbuf = sp_u32 + ((ph + 1) & 1) * SP_BYTES;
            for (int i = tid; i < 4096; i += 256) {
                int j = i >> 10, rs = i & 1023;
                int r = rs >> 3, seg = rs & 7;
                cp16(nbuf + j * SP_TAP + r * ROWB + seg * 16,
                     d_protA + ((size_t)(((ph + 1) * 4 + j) * 256 + p0 + r)) * LAT
                             + seg * 8);
            }
            CP_COMMIT();
        }

#pragma unroll
        for (int j = 0; j < 4; j++) {
            const int kk = ph * 4 + j;
            const uint32_t abase = buf + j * SP_TAP + a_off;
            const uint32_t bbase = sf_u32 + kk * ROWB + b_off;
#pragma unroll
            for (int cc = 0; cc < 4; cc++) {
                uint32_t a[4][4], bf[8][2];
#pragma unroll
                for (int mp = 0; mp < 2; mp++) {
                    LDSM4(a[2*mp][0], a[2*mp][1], a[2*mp][2], a[2*mp][3],
                          abase + mp * (32 * ROWB) + cc * 32);
                    LDSM4(a[2*mp+1][0], a[2*mp+1][1], a[2*mp+1][2], a[2*mp+1][3],
                          abase + (mp * 32 + 16) * ROWB + cc * 32);
                }
#pragma unroll
                for (int np = 0; np < 4; np++)
                    LDSM4(bf[2*np][0], bf[2*np][1], bf[2*np+1][0], bf[2*np+1][1],
                          bbase + np * (16 * ROWB) + cc * 32);
#pragma unroll
                for (int mt = 0; mt < 4; mt++)
#pragma unroll
                    for (int nt = 0; nt < 8; nt++)
                        mma16816(acc[mt][nt], a[mt], bf[nt]);
            }
        }

        if (ph < 3) {
            CP_WAIT0();
            __syncthreads();
        }
    }

    // ---- epilogue: dist = relu(s2 - 2*xp + p2), min over t ----
    const int g   = lane >> 2;
    const int tig = lane & 3;
#pragma unroll
    for (int mt = 0; mt < 4; mt++) {
#pragma unroll
        for (int half = 0; half < 2; half++) {
            const int pl = wm * 64 + mt * 16 + g + half * 8;
            const float pp = s_p2[pl];
            float mn = __int_as_float(0x7f800000);
#pragma unroll
            for (int nt = 0; nt < 8; nt++) {
#pragma unroll
                for (int e = 0; e < 2; e++) {
                    const int col = wn * 64 + nt * 8 + tig * 2 + e;
                    if (t0 + col < LO) {
                        float xp = acc[mt][nt][half * 2 + e];
                        float dd = fmaxf(s2s[col] - 2.f * xp + pp, 0.f);
                        mn = fminf(mn, dd);
                    }
                }
            }
            atomicMin(&s_md[pl], __float_as_uint(mn));
        }
    }
    __syncthreads();
    if (tid < 128 && p0 + tid < P_)
        atomicMin(&md[b * P_ + p0 + tid], s_md[tid]);
}

// ---------------------------------------------------------------------------
// Kernel 3: head
// ---------------------------------------------------------------------------
__global__ void head_kernel(const float* __restrict__ lw,
                            float* __restrict__ out)
{
    __shared__ float acts[B_ * P_];
    const unsigned* mdb = (const unsigned*)(out + B_ * C_);
    const int tid = threadIdx.x;
    for (int i = tid; i < B_ * P_; i += 320) {
        float m = __uint_as_float(mdb[i]);
        acts[i] = logf((m + 1.0f) / (m + EPS_));
    }
    __syncthreads();
    if (tid < B_ * C_) {
        int bb = tid / C_, c = tid % C_;
        float s = 0.f;
        for (int pidx = 0; pidx < P_; pidx++)
            s += acts[bb * P_ + pidx] * lw[c * P_ + pidx];
        out[bb * C_ + c] = s;
    }
}

// ---------------------------------------------------------------------------
extern "C" void kernel_launch(void* const* d_in, const int* in_sizes, int n_in,
                              void* d_out, int out_size)
{
    const float* x       = (const float*)d_in[0];
    const float* enc_w   = (const float*)d_in[1];
    const float* addon_w = (const float*)d_in[2];
    const float* protos  = (const float*)d_in[3];
    const float* last_w  = (const float*)d_in[4];
    float* out = (float*)d_out;

    cudaFuncSetAttribute(enc_addon_kernel,
                         cudaFuncAttributeMaxDynamicSharedMemorySize, ENC_DYN);
    cudaFuncSetAttribute(gemm_min_kernel,
                         cudaFuncAttributeMaxDynamicSharedMemorySize, GEMM_DYN);

    unsigned* md = (unsigned*)(out + B_ * C_);

    prep_kernel<<<PREP_GRID, 256>>>(protos, enc_w, addon_w, md);
    enc_addon_kernel<<<dim3(32, B_), 256, ENC_DYN>>>(x);
    gemm_min_kernel<<<dim3(32, 2, B_), 256, GEMM_DYN>>>(md);
    head_kernel<<<1, 320>>>(last_w, out);
}

// round 8
// speedup vs baseline: 8.3625x; 1.1660x over previous
#include <cuda_runtime.h>
#include <cuda_bf16.h>
#include <cstdint>

// ---------------------------------------------------------------------------
// ProtoTSNet on GB300 — round 8
//  - gemm: templated M-tile (128 + 80) to remove proto-padding MMAs (-19%)
//  - head: parallelized (32 blocks, warp-per-class)
//
// out[0..319]    = logits [32,10]
// out[320..6719] = min_distances [32,200]
// ---------------------------------------------------------------------------

#define B_     32
#define FIN    16
#define L_     8192
#define LAT    64
#define L1_    8190
#define P_     200
#define KP     16
#define LO     8175
#define C_     10
#define EPS_   1e-4f
#define TPAD   8224

// ---------------- static device scratch (allocation-free) -----------------
__device__ __nv_bfloat16 d_fT[B_ * TPAD * LAT];    // f [b][t][c], bf16
__device__ float         d_g [B_ * TPAD];          // sum_c f_bf16^2
__device__ __nv_bfloat16 d_protA[16 * 256 * LAT];  // protos [kk][p pad256][c]
__device__ float         d_p2[256];                // ||p||^2 (bf16-rounded)
__device__ __nv_bfloat16 d_w1[3 * 64 * 32];        // enc w  [tap][ch][16hi|16lo]
__device__ __nv_bfloat16 d_w2[64 * 128];           // addon w [ch2][64hi|64lo]

__device__ __forceinline__ uint32_t smem_u32(const void* p) {
    uint32_t a;
    asm("{ .reg .u64 t; cvta.to.shared.u64 t, %1; cvt.u32.u64 %0, t; }"
        : "=r"(a) : "l"(p));
    return a;
}
__device__ __forceinline__ void cp16(uint32_t s, const void* g) {
    asm volatile("cp.async.cg.shared.global [%0], [%1], 16;" :: "r"(s), "l"(g));
}
#define CP_COMMIT() asm volatile("cp.async.commit_group;" ::: "memory")
#define CP_WAIT0()  asm volatile("cp.async.wait_group 0;" ::: "memory")

__device__ __forceinline__ void mma16816(float* c, const uint32_t* a,
                                         const uint32_t* b)
{
    asm volatile(
        "mma.sync.aligned.m16n8k16.row.col.f32.bf16.bf16.f32 "
        "{%0,%1,%2,%3}, {%4,%5,%6,%7}, {%8,%9}, {%0,%1,%2,%3};"
        : "+f"(c[0]), "+f"(c[1]), "+f"(c[2]), "+f"(c[3])
        : "r"(a[0]), "r"(a[1]), "r"(a[2]), "r"(a[3]), "r"(b[0]), "r"(b[1]));
}
#define LDSM4(r0, r1, r2, r3, addr)                                           \
    asm volatile("ldmatrix.sync.aligned.m8n8.x4.shared.b16 {%0,%1,%2,%3},[%4];" \
        : "=r"(r0), "=r"(r1), "=r"(r2), "=r"(r3) : "r"(addr))

// ---------------------------------------------------------------------------
// Kernel 0: merged prep (block-range dispatch)
// ---------------------------------------------------------------------------
#define PREP_GRID 1305

__global__ void prep_kernel(const float* __restrict__ protos,
                            const float* __restrict__ ew,
                            const float* __restrict__ aw,
                            unsigned* __restrict__ md)
{
    const int blk = blockIdx.x;
    const int tid = threadIdx.x;

    if (blk < 1024) {                              // protA
        int idx = blk * 256 + tid;
        int c  = idx & 63;
        int pp = (idx >> 6) & 255;
        int kk = idx >> 14;
        float v = (pp < P_) ? protos[pp * (LAT * KP) + c * KP + kk] : 0.f;
        d_protA[idx] = __float2bfloat16(v);
    } else if (blk < 1224) {                       // p2
        const int p = blk - 1024;
        float s = 0.f;
        for (int i = tid; i < LAT * KP; i += 256) {
            float v = __bfloat162float(__float2bfloat16(protos[p * LAT * KP + i]));
            s += v * v;
        }
#pragma unroll
        for (int o = 16; o; o >>= 1) s += __shfl_xor_sync(0xffffffffu, s, o);
        __shared__ float red[8];
        if ((tid & 31) == 0) red[tid >> 5] = s;
        __syncthreads();
        if (tid == 0) {
            float ts = 0.f;
            for (int w = 0; w < 8; w++) ts += red[w];
            d_p2[p] = ts;
        }
    } else if (blk < 1249) {                       // init md
        int i = (blk - 1224) * 256 + tid;
        if (i < B_ * P_) md[i] = 0x7f800000u;
    } else if (blk < 1273) {                       // prep_w1
        int idx = (blk - 1249) * 256 + tid;
        if (idx < 3 * 64 * 32) {
            int pos = idx & 31, ch = (idx >> 5) & 63, tap = idx >> 11;
            int i = pos & 15;
            float w = ew[ch * 48 + i * 3 + tap];
            __nv_bfloat16 hi = __float2bfloat16(w);
            if (pos < 16) d_w1[idx] = hi;
            else          d_w1[idx] = __float2bfloat16(w - __bfloat162float(hi));
        }
    } else {                                       // prep_w2
        int idx = (blk - 1273) * 256 + tid;
        if (idx < 64 * 128) {
            int pos = idx & 127, ch2 = idx >> 7;
            int c = pos & 63;
            float w = aw[ch2 * 64 + c];
            __nv_bfloat16 hi = __float2bfloat16(w);
            if (pos < 64) d_w2[idx] = hi;
            else          d_w2[idx] = __float2bfloat16(w - __bfloat162float(hi));
        }
    }
}

// ---------------------------------------------------------------------------
// Kernel 1: enc conv(k=3)+ReLU + addon 1x1+ReLU via HMMA (split-bf16 3-pass)
// ---------------------------------------------------------------------------
#define B1_ROWB 80
#define OFF_B1  0
#define OFF_A1  20800
#define OFF_A2  36160
#define OFF_B2  53568
#define ENC_DYN 123200

__global__ void __launch_bounds__(256, 1)
enc_addon_kernel(const float* __restrict__ x)
{
    extern __shared__ char esm[];
    __shared__ float s_g2[256];

    const int b   = blockIdx.y;
    const int t0  = blockIdx.x * 256;
    const int tid = threadIdx.x;
    const int lane = tid & 31;
    const int wid  = tid >> 5;
    const int wm  = wid & 3;
    const int wn  = wid >> 2;
    const int sub = lane >> 3;
    const int lr  = lane & 7;
    const int g   = lane >> 2;
    const int tig = lane & 3;

    const uint32_t b1_u = smem_u32(esm) + OFF_B1;
    const uint32_t a1_u = smem_u32(esm) + OFF_A1;
    const uint32_t a2_u = smem_u32(esm) + OFF_A2;
    const uint32_t b2_u = smem_u32(esm) + OFF_B2;

    for (int idx = tid; idx < 16 * 260; idx += 256) {
        int i = idx / 260, r = idx - i * 260;
        int t = t0 + r;
        float v = (t < L_ && r < 258) ? x[(b * FIN + i) * L_ + t] : 0.f;
        __nv_bfloat16 hi = __float2bfloat16(v);
        __nv_bfloat16 lo = __float2bfloat16(v - __bfloat162float(hi));
        char* row = esm + OFF_B1 + r * B1_ROWB;
        *reinterpret_cast<__nv_bfloat16*>(row + i * 2)      = hi;
        *reinterpret_cast<__nv_bfloat16*>(row + 32 + i * 2) = lo;
    }
    for (int idx = tid; idx < 3 * 64 * 16; idx += 256) {
        int q = idx & 15, ch = (idx >> 4) & 63, tap = idx >> 10;
        *reinterpret_cast<uint32_t*>(esm + OFF_A1 + tap * (64 * B1_ROWB)
                                     + ch * B1_ROWB + q * 4) =
            reinterpret_cast<const uint32_t*>(d_w1)[idx];
    }
    for (int idx = tid; idx < 64 * 64; idx += 256) {
        int q = idx & 63, ch2 = idx >> 6;
        *reinterpret_cast<uint32_t*>(esm + OFF_A2 + ch2 * 272 + q * 4) =
            reinterpret_cast<const uint32_t*>(d_w2)[idx];
    }
    if (tid < 256) s_g2[tid] = 0.f;
    __syncthreads();

    // ---- stage 1: conv k=3 ----
    float acc1[4][4][4];
#pragma unroll
    for (int mt = 0; mt < 4; mt++)
#pragma unroll
        for (int nt = 0; nt < 4; nt++)
#pragma unroll
            for (int e = 0; e < 4; e++) acc1[mt][nt][e] = 0.f;

    const uint32_t a1row = (uint32_t)(wm * 64 + (sub & 1) * 8 + lr);
    const uint32_t a1colq = (uint32_t)((sub >> 1) * 16);
    const uint32_t w1row = (uint32_t)((wn * 32 + (sub >> 1) * 8 + lr) * B1_ROWB
                                      + (sub & 1) * 16);

#pragma unroll
    for (int tap = 0; tap < 3; tap++) {
#pragma unroll
        for (int pass = 0; pass < 3; pass++) {
            const uint32_t colA = (pass == 2) ? 32u : 0u;
            const uint32_t colB = (pass == 1) ? 32u : 0u;
            uint32_t bf[4][2];
            const uint32_t wb = a1_u + tap * (64 * B1_ROWB) + w1row + colB;
            LDSM4(bf[0][0], bf[0][1], bf[1][0], bf[1][1], wb);
            LDSM4(bf[2][0], bf[2][1], bf[3][0], bf[3][1], wb + 16 * B1_ROWB);
#pragma unroll
            for (int mt = 0; mt < 4; mt++) {
                uint32_t a[4];
                LDSM4(a[0], a[1], a[2], a[3],
                      b1_u + (a1row + mt * 16 + tap) * B1_ROWB + a1colq + colA);
#pragma unroll
                for (int nt = 0; nt < 4; nt++)
                    mma16816(acc1[mt][nt], a, bf[nt]);
            }
        }
    }

    // ---- epilogue 1 ----
#pragma unroll
    for (int mt = 0; mt < 4; mt++) {
#pragma unroll
        for (int nt = 0; nt < 4; nt++) {
#pragma unroll
            for (int eh = 0; eh < 2; eh++) {
                const int t  = wm * 64 + mt * 16 + g + eh * 8;
                const int ch = wn * 32 + nt * 8 + tig * 2;
                float v0 = fmaxf(acc1[mt][nt][eh * 2 + 0], 0.f);
                float v1 = fmaxf(acc1[mt][nt][eh * 2 + 1], 0.f);
                __nv_bfloat16 h0 = __float2bfloat16(v0);
                __nv_bfloat16 h1 = __float2bfloat16(v1);
                __nv_bfloat16 l0 = __float2bfloat16(v0 - __bfloat162float(h0));
                __nv_bfloat16 l1 = __float2bfloat16(v1 - __bfloat162float(h1));
                uint32_t hp = (uint32_t)__bfloat16_as_ushort(h0)
                            | ((uint32_t)__bfloat16_as_ushort(h1) << 16);
                uint32_t lp = (uint32_t)__bfloat16_as_ushort(l0)
                            | ((uint32_t)__bfloat16_as_ushort(l1) << 16);
                char* row = esm + OFF_B2 + t * 272;
                *reinterpret_cast<uint32_t*>(row + ch * 2)       = hp;
                *reinterpret_cast<uint32_t*>(row + 128 + ch * 2) = lp;
            }
        }
    }
    __syncthreads();

    // ---- stage 2: 1x1 addon ----
    float acc2[4][4][4];
#pragma unroll
    for (int mt = 0; mt < 4; mt++)
#pragma unroll
        for (int nt = 0; nt < 4; nt++)
#pragma unroll
            for (int e = 0; e < 4; e++) acc2[mt][nt][e] = 0.f;

    const uint32_t a2base = b2_u + (uint32_t)((wm * 64 + (sub & 1) * 8 + lr) * 272
                                              + (sub >> 1) * 16);
    const uint32_t w2base = a2_u + (uint32_t)((wn * 32 + (sub >> 1) * 8 + lr) * 272
                                              + (sub & 1) * 16);

#pragma unroll
    for (int step = 0; step < 12; step++) {
        const int kc   = step & 3;
        const int pass = step >> 2;
        const uint32_t colA = (pass == 2) ? (128u + kc * 32u) : (kc * 32u);
        const uint32_t colB = (pass == 1) ? (128u + kc * 32u) : (kc * 32u);
        uint32_t bf[4][2];
        LDSM4(bf[0][0], bf[0][1], bf[1][0], bf[1][1], w2base + colB);
        LDSM4(bf[2][0], bf[2][1], bf[3][0], bf[3][1], w2base + colB + 16 * 272);
#pragma unroll
        for (int mt = 0; mt < 4; mt++) {
            uint32_t a[4];
            LDSM4(a[0], a[1], a[2], a[3], a2base + mt * (16 * 272) + colA);
#pragma unroll
            for (int nt = 0; nt < 4; nt++)
                mma16816(acc2[mt][nt], a, bf[nt]);
        }
    }

    // ---- epilogue 2 ----
#pragma unroll
    for (int mt = 0; mt < 4; mt++) {
#pragma unroll
        for (int eh = 0; eh < 2; eh++) {
            const int t  = wm * 64 + mt * 16 + g + eh * 8;
            const int tg = t0 + t;
            float gp = 0.f;
#pragma unroll
            for (int nt = 0; nt < 4; nt++) {
                const int ch = wn * 32 + nt * 8 + tig * 2;
                float v0 = fmaxf(acc2[mt][nt][eh * 2 + 0], 0.f);
                float v1 = fmaxf(acc2[mt][nt][eh * 2 + 1], 0.f);
                __nv_bfloat162 h2 = __floats2bfloat162_rn(v0, v1);
                float r0 = __bfloat162float(__low2bfloat16(h2));
                float r1 = __bfloat162float(__high2bfloat16(h2));
                gp += r0 * r0 + r1 * r1;
                if (tg < L1_)
                    *reinterpret_cast<uint32_t*>(
                        d_fT + ((size_t)b * TPAD + tg) * LAT + ch) =
                        *reinterpret_cast<uint32_t*>(&h2);
            }
            atomicAdd(&s_g2[t], gp);
        }
    }
    __syncthreads();
    if (t0 + tid < L1_) d_g[b * TPAD + t0 + tid] = s_g2[tid];
}

// ---------------------------------------------------------------------------
// Kernel 2: HMMA GEMM + distance + min-reduce (templated M tile)
//   MBW = m16-blocks per warp, NWN = warps along N (8 warps total)
//   CTA M = MBW*(8/NWN)*16, CTA N = 256
// ---------------------------------------------------------------------------
#define NT_       256
#define FROWS     272
#define ROWB      144
#define SF_BYTES  (FROWS * ROWB)

template<int MBW, int NWN>
__global__ void __launch_bounds__(256, 1)
gemm_min_kernel(unsigned* __restrict__ md, int p0)
{
    constexpr int NWM  = 8 / NWN;            // warps along M
    constexpr int MB16 = MBW * NWM * 16;     // CTA M rows (128 or 80)
    constexpr int NTW  = 256 / (NWN * 8);    // n8-blocks per warp (8 or 4)
    constexpr int SP_TAPB = MB16 * ROWB;
    constexpr int SP_BYTESB = 4 * SP_TAPB;
    constexpr int LD_ITEMS = 4 * MB16 * 8;   // cp.async items per buffer

    extern __shared__ char dynsm[];
    char* sf = dynsm;
    char* sp = dynsm + SF_BYTES;

    __shared__ float    s_g[FROWS];
    __shared__ float    s2s[NT_];
    __shared__ float    s_p2[128];
    __shared__ unsigned s_md[128];

    const int b   = blockIdx.y;
    const int t0  = blockIdx.x * NT_;
    const int tid = threadIdx.x;
    const int lane = tid & 31;
    const int wid  = tid >> 5;
    const int wm = wid / NWN;
    const int wn = wid % NWN;
    const int sub = lane >> 3;
    const int lr  = lane & 7;

    const uint32_t sf_u32 = smem_u32(sf);
    const uint32_t sp_u32 = smem_u32(sp);

    const __nv_bfloat16* fT = d_fT + (size_t)b * TPAD * LAT;
    for (int i = tid; i < FROWS * 8; i += 256) {
        int r = i >> 3, seg = i & 7;
        cp16(sf_u32 + r * ROWB + seg * 16,
             fT + (size_t)(t0 + r) * LAT + seg * 8);
    }
    for (int i = tid; i < LD_ITEMS; i += 256) {
        int j = i / (MB16 * 8), rs = i % (MB16 * 8);
        int r = rs >> 3, seg = rs & 7;
        cp16(sp_u32 + j * SP_TAPB + r * ROWB + seg * 16,
             d_protA + ((size_t)(j * 256 + p0 + r)) * LAT + seg * 8);
    }
    CP_COMMIT();

    for (int i = tid; i < FROWS; i += 256) s_g[i] = d_g[b * TPAD + t0 + i];
    if (tid < 128) {
        s_p2[tid] = d_p2[p0 + tid];
        s_md[tid] = 0x7f800000u;
    }
    CP_WAIT0();
    __syncthreads();

    if (tid < NT_) {
        float s = 0.f;
#pragma unroll
        for (int k = 0; k < KP; k++) s += s_g[tid + k];
        s2s[tid] = s;
    }

    float acc[MBW][NTW][4];
#pragma unroll
    for (int mt = 0; mt < MBW; mt++)
#pragma unroll
        for (int nt = 0; nt < NTW; nt++)
#pragma unroll
            for (int e = 0; e < 4; e++) acc[mt][nt][e] = 0.f;

    const uint32_t a_off = (uint32_t)((wm * MBW * 16 + (sub & 1) * 8 + lr) * ROWB
                                      + (sub >> 1) * 16);
    const uint32_t b_off = (uint32_t)((wn * NTW * 8 + (sub >> 1) * 8 + lr) * ROWB
                                      + (sub & 1) * 16);

    for (int ph = 0; ph < 4; ph++) {
        const uint32_t buf = sp_u32 + (ph & 1) * SP_BYTESB;

        if (ph < 3) {
            const uint32_t nbuf = sp_u32 + ((ph + 1) & 1) * SP_BYTESB;
            for (int i = tid; i < LD_ITEMS; i += 256) {
                int j = i / (MB16 * 8), rs = i % (MB16 * 8);
                int r = rs >> 3, seg = rs & 7;
                cp16(nbuf + j * SP_TAPB + r * ROWB + seg * 16,
                     d_protA + ((size_t)(((ph + 1) * 4 + j) * 256 + p0 + r)) * LAT
                             + seg * 8);
            }
            CP_COMMIT();
        }

#pragma unroll
        for (int j = 0; j < 4; j++) {
            const int kk = ph * 4 + j;
            const uint32_t abase = buf + j * SP_TAPB + a_off;
            const uint32_t bbase = sf_u32 + kk * ROWB + b_off;
#pragma unroll
            for (int cc = 0; cc < 4; cc++) {
                uint32_t a[MBW][4], bf[NTW][2];
#pragma unroll
                for (int mb = 0; mb < MBW; mb++)
                    LDSM4(a[mb][0], a[mb][1], a[mb][2], a[mb][3],
                          abase + mb * (16 * ROWB) + cc * 32);
#pragma unroll
                for (int np = 0; np < NTW / 2; np++)
                    LDSM4(bf[2*np][0], bf[2*np][1], bf[2*np+1][0], bf[2*np+1][1],
                          bbase + np * (16 * ROWB) + cc * 32);
#pragma unroll
                for (int mt = 0; mt < MBW; mt++)
#pragma unroll
                    for (int nt = 0; nt < NTW; nt++)
                        mma16816(acc[mt][nt], a[mt], bf[nt]);
            }
        }

        if (ph < 3) {
            CP_WAIT0();
            __syncthreads();
        }
    }

    // ---- epilogue: dist = relu(s2 - 2*xp + p2), min over t ----
    const int g   = lane >> 2;
    const int tig = lane & 3;
#pragma unroll
    for (int mt = 0; mt < MBW; mt++) {
#pragma unroll
        for (int half = 0; half < 2; half++) {
            const int pl = wm * MBW * 16 + mt * 16 + g + half * 8;
            const float pp = s_p2[pl];
            float mn = __int_as_float(0x7f800000);
#pragma unroll
            for (int nt = 0; nt < NTW; nt++) {
#pragma unroll
                for (int e = 0; e < 2; e++) {
                    const int col = wn * NTW * 8 + nt * 8 + tig * 2 + e;
                    if (t0 + col < LO) {
                        float xp = acc[mt][nt][half * 2 + e];
                        float dd = fmaxf(s2s[col] - 2.f * xp + pp, 0.f);
                        mn = fminf(mn, dd);
                    }
                }
            }
            atomicMin(&s_md[pl], __float_as_uint(mn));
        }
    }
    __syncthreads();
    if (tid < MB16 && p0 + tid < P_)
        atomicMin(&md[b * P_ + p0 + tid], s_md[tid]);
}

#define GEMM_DYN0 (SF_BYTES + 2 * 4 * 128 * ROWB)   // 186624
#define GEMM_DYN1 (SF_BYTES + 2 * 4 * 80  * ROWB)   // 131328

// ---------------------------------------------------------------------------
// Kernel 3: head — one block per batch, warp per class
// ---------------------------------------------------------------------------
__global__ void head_kernel(const float* __restrict__ lw,
                            float* __restrict__ out)
{
    __shared__ float acts[P_];
    const int b   = blockIdx.x;
    const int tid = threadIdx.x;     // 320
    const unsigned* mdb = (const unsigned*)(out + B_ * C_) + b * P_;

    if (tid < P_) {
        float m = __uint_as_float(mdb[tid]);
        acts[tid] = logf((m + 1.0f) / (m + EPS_));
    }
    __syncthreads();

    const int c    = tid >> 5;       // class (10 warps)
    const int lane = tid & 31;
    float s = 0.f;
    for (int p = lane; p < P_; p += 32)
        s += acts[p] * lw[c * P_ + p];
#pragma unroll
    for (int o = 16; o; o >>= 1) s += __shfl_xor_sync(0xffffffffu, s, o);
    if (lane == 0) out[b * C_ + c] = s;
}

// ---------------------------------------------------------------------------
extern "C" void kernel_launch(void* const* d_in, const int* in_sizes, int n_in,
                              void* d_out, int out_size)
{
    const float* x       = (const float*)d_in[0];
    const float* enc_w   = (const float*)d_in[1];
    const float* addon_w = (const float*)d_in[2];
    const float* protos  = (const float*)d_in[3];
    const float* last_w  = (const float*)d_in[4];
    float* out = (float*)d_out;

    cudaFuncSetAttribute(enc_addon_kernel,
                         cudaFuncAttributeMaxDynamicSharedMemorySize, ENC_DYN);
    cudaFuncSetAttribute(gemm_min_kernel<4, 4>,
                         cudaFuncAttributeMaxDynamicSharedMemorySize, GEMM_DYN0);
    cudaFuncSetAttribute(gemm_min_kernel<5, 8>,
                         cudaFuncAttributeMaxDynamicSharedMemorySize, GEMM_DYN1);

    unsigned* md = (unsigned*)(out + B_ * C_);

    prep_kernel<<<PREP_GRID, 256>>>(protos, enc_w, addon_w, md);
    enc_addon_kernel<<<dim3(32, B_), 256, ENC_DYN>>>(x);
    gemm_min_kernel<4, 4><<<dim3(32, B_), 256, GEMM_DYN0>>>(md, 0);    // p 0-127
    gemm_min_kernel<5, 8><<<dim3(32, B_), 256, GEMM_DYN1>>>(md, 128);  // p 128-199
    head_kernel<<<B_, 320>>>(last_w, out);
}